// round 1
// baseline (speedup 1.0000x reference)
#include <cuda_runtime.h>
#include <math.h>

#define HID   1024
#define VOCAB 32000
#define SEQ   64
#define NL    2
#define BOS   1

// ---------------- device scratch (no allocations allowed) ----------------
__device__ float d_h[2][NL][HID];   // [buf][layer][hid], double-buffered h
__device__ float d_c[NL][HID];      // cell state (in-place per hidden unit is safe)
__device__ float d_logits[VOCAB];
#define NB_LOGITS (VOCAB / 8)       // 4000 blocks, 8 rows (warps) per block
__device__ float d_pmax[NB_LOGITS];
__device__ float d_psum[NB_LOGITS];
__device__ int   d_pidx[NB_LOGITS];
__device__ int   d_token;
__device__ float d_M, d_logS;

// ---------------- init: zero h and c ----------------
__global__ void init_state_kernel() {
    int i = blockIdx.x * blockDim.x + threadIdx.x;
    if (i < 2 * NL * HID) ((float*)d_h)[i] = 0.0f;
    if (i < NL * HID)     ((float*)d_c)[i] = 0.0f;
}

__device__ __forceinline__ float sigmoidf_(float x) {
    return 1.0f / (1.0f + expf(-x));
}

// ---------------- fused LSTM layer step ----------------
// One warp per hidden unit j: computes all 4 gates
//   g_q = dot(Wih[q*H+j], x) + dot(Whh[q*H+j], h_in) + bih[q*H+j] + bhh[q*H+j]
// then updates c[layer][j] and d_h[buf_out][layer][j].
// x selection:
//   mode 0: x = d_h[buf_out][0]           (layer-1 input = layer-0 new h)
//   mode 1: x = emb + tok_arr[tok_idx]*H  (encoder, token from src[])
//   mode 2: x = emb + tok_idx*H           (immediate token, e.g. BOS)
//   mode 3: x = emb + d_token*H           (decoder, previous argmax)
__global__ void __launch_bounds__(256)
lstm_layer_kernel(const float* __restrict__ Wih, const float* __restrict__ Whh,
                  const float* __restrict__ bih, const float* __restrict__ bhh,
                  const float* __restrict__ emb, const int* __restrict__ tok_arr,
                  int tok_idx, int mode, int buf_in, int buf_out, int layer)
{
    int gwarp = (blockIdx.x * blockDim.x + threadIdx.x) >> 5;  // 0..1023
    int lane  = threadIdx.x & 31;
    if (gwarp >= HID) return;

    const float* x;
    if (mode == 0)      x = &d_h[buf_out][0][0];
    else if (mode == 1) x = emb + (size_t)tok_arr[tok_idx] * HID;
    else if (mode == 2) x = emb + (size_t)tok_idx * HID;
    else                x = emb + (size_t)d_token * HID;

    const float* h_in = &d_h[buf_in][layer][0];

    const float4* x4 = (const float4*)x;
    const float4* h4 = (const float4*)h_in;

    // row pointers for the 4 gates of this hidden unit
    const float4* w4[4];
    const float4* u4[4];
#pragma unroll
    for (int q = 0; q < 4; q++) {
        w4[q] = (const float4*)(Wih + (size_t)(q * HID + gwarp) * HID);
        u4[q] = (const float4*)(Whh + (size_t)(q * HID + gwarp) * HID);
    }

    float acc[4] = {0.f, 0.f, 0.f, 0.f};
#pragma unroll
    for (int i = 0; i < 8; i++) {
        int idx = i * 32 + lane;
        float4 xv = x4[idx];
        float4 hv = h4[idx];
#pragma unroll
        for (int q = 0; q < 4; q++) {
            float4 wv = w4[q][idx];
            float4 uv = u4[q][idx];
            acc[q] += wv.x * xv.x + wv.y * xv.y + wv.z * xv.z + wv.w * xv.w;
            acc[q] += uv.x * hv.x + uv.y * hv.y + uv.z * hv.z + uv.w * hv.w;
        }
    }
#pragma unroll
    for (int off = 16; off; off >>= 1) {
#pragma unroll
        for (int q = 0; q < 4; q++)
            acc[q] += __shfl_xor_sync(0xffffffffu, acc[q], off);
    }

    if (lane == 0) {
        float gi = acc[0] + bih[0 * HID + gwarp] + bhh[0 * HID + gwarp];
        float gf = acc[1] + bih[1 * HID + gwarp] + bhh[1 * HID + gwarp];
        float gg = acc[2] + bih[2 * HID + gwarp] + bhh[2 * HID + gwarp];
        float go = acc[3] + bih[3 * HID + gwarp] + bhh[3 * HID + gwarp];
        float i_ = sigmoidf_(gi);
        float f_ = sigmoidf_(gf);
        float g_ = tanhf(gg);
        float o_ = sigmoidf_(go);
        float cn = f_ * d_c[layer][gwarp] + i_ * g_;
        d_c[layer][gwarp]       = cn;
        d_h[buf_out][layer][gwarp] = o_ * tanhf(cn);
    }
}

// ---------------- logits matvec + per-block softmax partials ----------------
// One warp per vocab row; 8 rows per block. Writes logits and the block's
// (max, argmax, sum exp(x - blockmax)) partials.
__global__ void __launch_bounds__(256)
logits_kernel(const float* __restrict__ W, const float* __restrict__ b,
              int buf_h)
{
    int wib  = threadIdx.x >> 5;     // 0..7
    int lane = threadIdx.x & 31;
    int row  = blockIdx.x * 8 + wib;

    const float4* h4 = (const float4*)&d_h[buf_h][NL - 1][0];
    const float4* w4 = (const float4*)(W + (size_t)row * HID);

    float acc = 0.f;
#pragma unroll
    for (int i = 0; i < 8; i++) {
        int idx = i * 32 + lane;
        float4 wv = w4[idx];
        float4 hv = h4[idx];
        acc += wv.x * hv.x + wv.y * hv.y + wv.z * hv.z + wv.w * hv.w;
    }
#pragma unroll
    for (int off = 16; off; off >>= 1)
        acc += __shfl_xor_sync(0xffffffffu, acc, off);

    __shared__ float s[8];
    if (lane == 0) {
        acc += b[row];
        d_logits[row] = acc;
        s[wib] = acc;
    }
    __syncthreads();
    if (threadIdx.x == 0) {
        float m = s[0]; int mi = 0;
#pragma unroll
        for (int k = 1; k < 8; k++)
            if (s[k] > m) { m = s[k]; mi = k; }
        float sum = 0.f;
#pragma unroll
        for (int k = 0; k < 8; k++) sum += expf(s[k] - m);
        d_pmax[blockIdx.x] = m;
        d_psum[blockIdx.x] = sum;
        d_pidx[blockIdx.x] = blockIdx.x * 8 + mi;
    }
}

// ---------------- finalize: global max/argmax/logsumexp + next token ----------------
__global__ void __launch_bounds__(256)
finalize_kernel()
{
    __shared__ float sm[256];
    __shared__ int   si[256];
    __shared__ float ss[256];
    int tid = threadIdx.x;

    float m = -3.0e38f; int mi = 0x7fffffff;
    for (int bk = tid; bk < NB_LOGITS; bk += 256) {
        float v = d_pmax[bk];
        int   ix = d_pidx[bk];
        if (v > m || (v == m && ix < mi)) { m = v; mi = ix; }
    }
    sm[tid] = m; si[tid] = mi;
    __syncthreads();
    for (int s = 128; s; s >>= 1) {
        if (tid < s) {
            if (sm[tid + s] > sm[tid] ||
                (sm[tid + s] == sm[tid] && si[tid + s] < si[tid])) {
                sm[tid] = sm[tid + s];
                si[tid] = si[tid + s];
            }
        }
        __syncthreads();
    }
    float M = sm[0];
    __syncthreads();

    float S = 0.f;
    for (int bk = tid; bk < NB_LOGITS; bk += 256)
        S += d_psum[bk] * expf(d_pmax[bk] - M);
    ss[tid] = S;
    __syncthreads();
    for (int s = 128; s; s >>= 1) {
        if (tid < s) ss[tid] += ss[tid + s];
        __syncthreads();
    }
    if (tid == 0) {
        d_M     = M;
        d_logS  = logf(ss[0]);
        d_token = si[0];
    }
}

// ---------------- write log-probs for this decoder step ----------------
__global__ void __launch_bounds__(256)
write_logp_kernel(float* __restrict__ out)
{
    int i = blockIdx.x * blockDim.x + threadIdx.x;
    if (i < VOCAB) out[i] = d_logits[i] - d_M - d_logS;
}

// ---------------- host orchestration (graph-capturable, launches only) ----------------
extern "C" void kernel_launch(void* const* d_in, const int* in_sizes, int n_in,
                              void* d_out, int out_size)
{
    (void)in_sizes; (void)n_in;
    const int*   src     = (const int*)  d_in[0];
    // d_in[1] = tgt (unused: only its fixed length SEQ matters)
    const float* emb_enc = (const float*)d_in[2];
    const float* enc_Wih = (const float*)d_in[3];
    const float* enc_Whh = (const float*)d_in[4];
    const float* enc_bih = (const float*)d_in[5];
    const float* enc_bhh = (const float*)d_in[6];
    const float* emb_dec = (const float*)d_in[7];
    const float* dec_Wih = (const float*)d_in[8];
    const float* dec_Whh = (const float*)d_in[9];
    const float* dec_bih = (const float*)d_in[10];
    const float* dec_bhh = (const float*)d_in[11];
    const float* out_W   = (const float*)d_in[12];
    const float* out_b   = (const float*)d_in[13];
    float* out = (float*)d_out;
    (void)out_size;

    const size_t WOFF = (size_t)4 * HID * HID;   // per-layer weight stride
    const size_t BOFF = (size_t)4 * HID;         // per-layer bias stride

    init_state_kernel<<<24, 256>>>();

    int p = 0;  // h buffer parity: read p, write 1-p

    // ---- encoder ----
    for (int t = 0; t < SEQ; t++) {
        lstm_layer_kernel<<<128, 256>>>(
            enc_Wih, enc_Whh, enc_bih, enc_bhh,
            emb_enc, src, t, /*mode=*/1, p, 1 - p, /*layer=*/0);
        lstm_layer_kernel<<<128, 256>>>(
            enc_Wih + WOFF, enc_Whh + WOFF, enc_bih + BOFF, enc_bhh + BOFF,
            nullptr, nullptr, 0, /*mode=*/0, p, 1 - p, /*layer=*/1);
        p ^= 1;
    }

    // ---- decoder (greedy autoregressive) ----
    for (int t = 0; t < SEQ; t++) {
        int mode0 = (t == 0) ? 2 : 3;
        int tokix = (t == 0) ? BOS : 0;
        lstm_layer_kernel<<<128, 256>>>(
            dec_Wih, dec_Whh, dec_bih, dec_bhh,
            emb_dec, nullptr, tokix, mode0, p, 1 - p, /*layer=*/0);
        lstm_layer_kernel<<<128, 256>>>(
            dec_Wih + WOFF, dec_Whh + WOFF, dec_bih + BOFF, dec_bhh + BOFF,
            nullptr, nullptr, 0, /*mode=*/0, p, 1 - p, /*layer=*/1);

        logits_kernel<<<NB_LOGITS, 256>>>(out_W, out_b, 1 - p);
        finalize_kernel<<<1, 256>>>();
        write_logp_kernel<<<(VOCAB + 255) / 256, 256>>>(out + (size_t)t * VOCAB);

        p ^= 1;
    }
}

// round 2
// speedup vs baseline: 1.3142x; 1.3142x over previous
#include <cuda_runtime.h>
#include <math.h>

#define HID   1024
#define VOCAB 32000
#define SEQ   64
#define NL    2
#define BOS   1

// ---------------- device scratch (no allocations allowed) ----------------
__device__ float d_h[2][NL][HID];   // [buf][layer][hid], double-buffered h
__device__ float d_c[NL][HID];      // cell state
__device__ float d_logits[VOCAB];
#define NB_LOGITS (VOCAB / 8)       // 4000 blocks, 8 rows (warps) per block
__device__ float d_pmax[NB_LOGITS];
__device__ float d_psum[NB_LOGITS];
__device__ int   d_pidx[NB_LOGITS];
__device__ int   d_token;
__device__ float d_M, d_logS;

// ---------------- init: zero h and c ----------------
__global__ void init_state_kernel() {
    int i = blockIdx.x * blockDim.x + threadIdx.x;
    if (i < 2 * NL * HID) ((float*)d_h)[i] = 0.0f;
    if (i < NL * HID)     ((float*)d_c)[i] = 0.0f;
}

__device__ __forceinline__ float sigmoidf_(float x) {
    return 1.0f / (1.0f + expf(-x));
}

// ---------------- fused LSTM layer step ----------------
// One warp per GATE ROW (4096 rows total): warp computes
//   dot(Wih[row], x) + dot(Whh[row], h_in)
// Block = 8 warps = 4 gates x 2 hidden units; gate partials combined in smem,
// pointwise c/h update done by 2 threads of the block.
// x selection:
//   mode 0: x = d_h[buf_out][0]           (layer-1 input = layer-0 new h)
//   mode 1: x = emb + tok_arr[tok_idx]*H  (encoder, token from src[])
//   mode 2: x = emb + tok_idx*H           (immediate token, e.g. BOS)
//   mode 3: x = emb + d_token*H           (decoder, previous argmax)
__global__ void __launch_bounds__(256, 4)
lstm_layer_kernel(const float* __restrict__ Wih, const float* __restrict__ Whh,
                  const float* __restrict__ bih, const float* __restrict__ bhh,
                  const float* __restrict__ emb, const int* __restrict__ tok_arr,
                  int tok_idx, int mode, int buf_in, int buf_out, int layer)
{
    __shared__ float sx[HID];
    __shared__ float sh[HID];
    __shared__ float sg[8];

    const float* x;
    if (mode == 0)      x = &d_h[buf_out][0][0];
    else if (mode == 1) x = emb + (size_t)tok_arr[tok_idx] * HID;
    else if (mode == 2) x = emb + (size_t)tok_idx * HID;
    else                x = emb + (size_t)d_token * HID;

    const float* h_in = &d_h[buf_in][layer][0];

    // cooperative stage of x and h: 256 threads x 1 float4 each
    {
        float4* sx4 = (float4*)sx;
        float4* sh4 = (float4*)sh;
        sx4[threadIdx.x] = ((const float4*)x)[threadIdx.x];
        sh4[threadIdx.x] = ((const float4*)h_in)[threadIdx.x];
    }
    __syncthreads();

    int wib  = threadIdx.x >> 5;   // 0..7
    int lane = threadIdx.x & 31;
    int u    = wib & 1;            // which of the 2 hidden units
    int gate = wib >> 1;           // 0..3 (i, f, g, o)
    int unit = blockIdx.x * 2 + u;
    size_t row_off = (size_t)(gate * HID + unit) * HID;

    const float4* w4  = (const float4*)(Wih + row_off);
    const float4* v4  = (const float4*)(Whh + row_off);
    const float4* sx4 = (const float4*)sx;
    const float4* sh4 = (const float4*)sh;

    float acc = 0.f;
#pragma unroll
    for (int i = 0; i < 8; i++) {
        int idx = i * 32 + lane;
        float4 wv = w4[idx];
        float4 uv = v4[idx];
        float4 xv = sx4[idx];
        float4 hv = sh4[idx];
        acc += wv.x * xv.x + wv.y * xv.y + wv.z * xv.z + wv.w * xv.w;
        acc += uv.x * hv.x + uv.y * hv.y + uv.z * hv.z + uv.w * hv.w;
    }
#pragma unroll
    for (int off = 16; off; off >>= 1)
        acc += __shfl_xor_sync(0xffffffffu, acc, off);

    if (lane == 0) sg[wib] = acc;
    __syncthreads();

    if (threadIdx.x < 2) {
        int un = blockIdx.x * 2 + threadIdx.x;
        float gi = sg[0 + threadIdx.x] + bih[0 * HID + un] + bhh[0 * HID + un];
        float gf = sg[2 + threadIdx.x] + bih[1 * HID + un] + bhh[1 * HID + un];
        float gg = sg[4 + threadIdx.x] + bih[2 * HID + un] + bhh[2 * HID + un];
        float go = sg[6 + threadIdx.x] + bih[3 * HID + un] + bhh[3 * HID + un];
        float i_ = sigmoidf_(gi);
        float f_ = sigmoidf_(gf);
        float g_ = tanhf(gg);
        float o_ = sigmoidf_(go);
        float cn = f_ * d_c[layer][un] + i_ * g_;
        d_c[layer][un]            = cn;
        d_h[buf_out][layer][un]   = o_ * tanhf(cn);
    }
}

// ---------------- logits matvec + per-block softmax partials ----------------
__global__ void __launch_bounds__(256, 4)
logits_kernel(const float* __restrict__ W, const float* __restrict__ b,
              int buf_h)
{
    __shared__ float shv[HID];
    __shared__ float s[8];

    {
        float4* sh4 = (float4*)shv;
        sh4[threadIdx.x] = ((const float4*)&d_h[buf_h][NL - 1][0])[threadIdx.x];
    }
    __syncthreads();

    int wib  = threadIdx.x >> 5;     // 0..7
    int lane = threadIdx.x & 31;
    int row  = blockIdx.x * 8 + wib;

    const float4* h4 = (const float4*)shv;
    const float4* w4 = (const float4*)(W + (size_t)row * HID);

    float acc = 0.f;
#pragma unroll
    for (int i = 0; i < 8; i++) {
        int idx = i * 32 + lane;
        float4 wv = w4[idx];
        float4 hv = h4[idx];
        acc += wv.x * hv.x + wv.y * hv.y + wv.z * hv.z + wv.w * hv.w;
    }
#pragma unroll
    for (int off = 16; off; off >>= 1)
        acc += __shfl_xor_sync(0xffffffffu, acc, off);

    if (lane == 0) {
        acc += b[row];
        d_logits[row] = acc;
        s[wib] = acc;
    }
    __syncthreads();
    if (threadIdx.x == 0) {
        float m = s[0]; int mi = 0;
#pragma unroll
        for (int k = 1; k < 8; k++)
            if (s[k] > m) { m = s[k]; mi = k; }
        float sum = 0.f;
#pragma unroll
        for (int k = 0; k < 8; k++) sum += expf(s[k] - m);
        d_pmax[blockIdx.x] = m;
        d_psum[blockIdx.x] = sum;
        d_pidx[blockIdx.x] = blockIdx.x * 8 + mi;
    }
}

// ---------------- finalize: global max/argmax/logsumexp + next token ----------------
__global__ void __launch_bounds__(256)
finalize_kernel()
{
    __shared__ float sm[256];
    __shared__ int   si[256];
    __shared__ float ss[256];
    int tid = threadIdx.x;

    float m = -3.0e38f; int mi = 0x7fffffff;
    for (int bk = tid; bk < NB_LOGITS; bk += 256) {
        float v = d_pmax[bk];
        int   ix = d_pidx[bk];
        if (v > m || (v == m && ix < mi)) { m = v; mi = ix; }
    }
    sm[tid] = m; si[tid] = mi;
    __syncthreads();
    for (int s = 128; s; s >>= 1) {
        if (tid < s) {
            if (sm[tid + s] > sm[tid] ||
                (sm[tid + s] == sm[tid] && si[tid + s] < si[tid])) {
                sm[tid] = sm[tid + s];
                si[tid] = si[tid + s];
            }
        }
        __syncthreads();
    }
    float M = sm[0];
    __syncthreads();

    float S = 0.f;
    for (int bk = tid; bk < NB_LOGITS; bk += 256)
        S += d_psum[bk] * expf(d_pmax[bk] - M);
    ss[tid] = S;
    __syncthreads();
    for (int s = 128; s; s >>= 1) {
        if (tid < s) ss[tid] += ss[tid + s];
        __syncthreads();
    }
    if (tid == 0) {
        d_M     = M;
        d_logS  = logf(ss[0]);
        d_token = si[0];
    }
}

// ---------------- write log-probs for this decoder step ----------------
__global__ void __launch_bounds__(256)
write_logp_kernel(float* __restrict__ out)
{
    int i = blockIdx.x * blockDim.x + threadIdx.x;
    if (i < VOCAB) out[i] = d_logits[i] - d_M - d_logS;
}

// ---------------- host orchestration (graph-capturable, launches only) ----------------
extern "C" void kernel_launch(void* const* d_in, const int* in_sizes, int n_in,
                              void* d_out, int out_size)
{
    (void)in_sizes; (void)n_in;
    const int*   src     = (const int*)  d_in[0];
    // d_in[1] = tgt (unused: only its fixed length SEQ matters)
    const float* emb_enc = (const float*)d_in[2];
    const float* enc_Wih = (const float*)d_in[3];
    const float* enc_Whh = (const float*)d_in[4];
    const float* enc_bih = (const float*)d_in[5];
    const float* enc_bhh = (const float*)d_in[6];
    const float* emb_dec = (const float*)d_in[7];
    const float* dec_Wih = (const float*)d_in[8];
    const float* dec_Whh = (const float*)d_in[9];
    const float* dec_bih = (const float*)d_in[10];
    const float* dec_bhh = (const float*)d_in[11];
    const float* out_W   = (const float*)d_in[12];
    const float* out_b   = (const float*)d_in[13];
    float* out = (float*)d_out;
    (void)out_size;

    const size_t WOFF = (size_t)4 * HID * HID;   // per-layer weight stride
    const size_t BOFF = (size_t)4 * HID;         // per-layer bias stride

    init_state_kernel<<<24, 256>>>();

    int p = 0;  // h buffer parity: read p, write 1-p

    // ---- encoder ----
    for (int t = 0; t < SEQ; t++) {
        lstm_layer_kernel<<<HID / 2, 256>>>(
            enc_Wih, enc_Whh, enc_bih, enc_bhh,
            emb_enc, src, t, /*mode=*/1, p, 1 - p, /*layer=*/0);
        lstm_layer_kernel<<<HID / 2, 256>>>(
            enc_Wih + WOFF, enc_Whh + WOFF, enc_bih + BOFF, enc_bhh + BOFF,
            nullptr, nullptr, 0, /*mode=*/0, p, 1 - p, /*layer=*/1);
        p ^= 1;
    }

    // ---- decoder (greedy autoregressive) ----
    for (int t = 0; t < SEQ; t++) {
        int mode0 = (t == 0) ? 2 : 3;
        int tokix = (t == 0) ? BOS : 0;
        lstm_layer_kernel<<<HID / 2, 256>>>(
            dec_Wih, dec_Whh, dec_bih, dec_bhh,
            emb_dec, nullptr, tokix, mode0, p, 1 - p, /*layer=*/0);
        lstm_layer_kernel<<<HID / 2, 256>>>(
            dec_Wih + WOFF, dec_Whh + WOFF, dec_bih + BOFF, dec_bhh + BOFF,
            nullptr, nullptr, 0, /*mode=*/0, p, 1 - p, /*layer=*/1);

        logits_kernel<<<NB_LOGITS, 256>>>(out_W, out_b, 1 - p);
        finalize_kernel<<<1, 256>>>();
        write_logp_kernel<<<(VOCAB + 255) / 256, 256>>>(out + (size_t)t * VOCAB);

        p ^= 1;
    }
}

// round 3
// speedup vs baseline: 1.3158x; 1.0012x over previous
#include <cuda_runtime.h>
#include <math.h>

#define HID   1024
#define VOCAB 32000
#define SEQ   64
#define NL    2
#define BOS   1

// ---------------- device scratch ----------------
__device__ float d_h[2][NL][HID];
__device__ float d_c[NL][HID];
__device__ float d_logits[VOCAB];
__device__ float d_pre[SEQ][4 * HID];   // encoder layer-0 Wih@x precompute (1 MB)
#define NB_LOGITS (VOCAB / 8)           // 4000 blocks
__device__ float d_pmax[NB_LOGITS];
__device__ float d_psum[NB_LOGITS];
__device__ int   d_pidx[NB_LOGITS];
__device__ unsigned int d_count;
__device__ int   d_token;
__device__ float d_M, d_logS;

// ---------------- init ----------------
__global__ void init_state_kernel() {
    int i = blockIdx.x * blockDim.x + threadIdx.x;
    if (i < 2 * NL * HID) ((float*)d_h)[i] = 0.0f;
    if (i < NL * HID)     ((float*)d_c)[i] = 0.0f;
    if (i == 0)           d_count = 0u;
}

__device__ __forceinline__ float sigmoidf_(float x) {
    return 1.0f / (1.0f + expf(-x));
}

// ---------------- encoder layer-0 input GEMM ----------------
// pre[t][row] = dot(Wih0[row], emb[src[t]])  for all 64 t, 4096 rows.
// block: 8 warps; warp w -> row blockIdx.x*8+w; token tile blockIdx.y (8 tokens).
__global__ void __launch_bounds__(256, 4)
enc_pre_kernel(const float* __restrict__ Wih, const float* __restrict__ emb,
               const int* __restrict__ src)
{
    __shared__ float sx[8][HID];          // 32 KB
    int tid = threadIdx.x;

    // stage 8 token embeddings
    for (int j = 0; j < 8; j++) {
        int tok = src[blockIdx.y * 8 + j];
        ((float4*)sx[j])[tid] = ((const float4*)(emb + (size_t)tok * HID))[tid];
    }
    __syncthreads();

    int wib  = tid >> 5;
    int lane = tid & 31;
    int row  = blockIdx.x * 8 + wib;
    const float4* w4 = (const float4*)(Wih + (size_t)row * HID);

    float acc[8] = {0.f,0.f,0.f,0.f,0.f,0.f,0.f,0.f};
#pragma unroll
    for (int i = 0; i < 8; i++) {
        int idx = i * 32 + lane;
        float4 wv = w4[idx];
#pragma unroll
        for (int t = 0; t < 8; t++) {
            float4 xv = ((const float4*)sx[t])[idx];
            acc[t] += wv.x * xv.x + wv.y * xv.y + wv.z * xv.z + wv.w * xv.w;
        }
    }
#pragma unroll
    for (int off = 16; off; off >>= 1)
#pragma unroll
        for (int t = 0; t < 8; t++)
            acc[t] += __shfl_xor_sync(0xffffffffu, acc[t], off);

    if (lane == 0) {
#pragma unroll
        for (int t = 0; t < 8; t++)
            d_pre[blockIdx.y * 8 + t][row] = acc[t];
    }
}

// ---------------- fused LSTM layer step ----------------
// One warp per gate row; block = 8 warps = 4 gates x 2 units.
// mode: 0 = x from d_h[buf_out][0] (layer-1); 2 = emb+tok_idx*H; 3 = emb+d_token*H;
//       4 = pre-mode (encoder L0): Wih@x comes from d_pre[tok_idx], only Whh dot here.
// out_prev: if non-null, first VOCAB global threads write previous-step logp first.
__global__ void __launch_bounds__(256, 4)
lstm_layer_kernel(const float* __restrict__ Wih, const float* __restrict__ Whh,
                  const float* __restrict__ bih, const float* __restrict__ bhh,
                  const float* __restrict__ emb, float* __restrict__ out_prev,
                  int tok_idx, int mode, int buf_in, int buf_out, int layer)
{
    if (out_prev) {
        int gid = blockIdx.x * blockDim.x + threadIdx.x;
        if (gid < VOCAB) out_prev[gid] = d_logits[gid] - d_M - d_logS;
    }

    __shared__ float sx[HID];
    __shared__ float sh[HID];
    __shared__ float sg[8];

    const float* h_in = &d_h[buf_in][layer][0];
    ((float4*)sh)[threadIdx.x] = ((const float4*)h_in)[threadIdx.x];

    if (mode != 4) {
        const float* x;
        if (mode == 0)      x = &d_h[buf_out][0][0];
        else if (mode == 2) x = emb + (size_t)tok_idx * HID;
        else                x = emb + (size_t)d_token * HID;
        ((float4*)sx)[threadIdx.x] = ((const float4*)x)[threadIdx.x];
    }
    __syncthreads();

    int wib  = threadIdx.x >> 5;
    int lane = threadIdx.x & 31;
    int u    = wib & 1;
    int gate = wib >> 1;
    int unit = blockIdx.x * 2 + u;
    size_t row_off = (size_t)(gate * HID + unit) * HID;

    const float4* v4  = (const float4*)(Whh + row_off);
    const float4* sh4 = (const float4*)sh;

    float acc = 0.f;
    if (mode == 4) {
#pragma unroll
        for (int i = 0; i < 8; i++) {
            int idx = i * 32 + lane;
            float4 uv = v4[idx];
            float4 hv = sh4[idx];
            acc += uv.x * hv.x + uv.y * hv.y + uv.z * hv.z + uv.w * hv.w;
        }
    } else {
        const float4* w4  = (const float4*)(Wih + row_off);
        const float4* sx4 = (const float4*)sx;
#pragma unroll
        for (int i = 0; i < 8; i++) {
            int idx = i * 32 + lane;
            float4 wv = w4[idx];
            float4 uv = v4[idx];
            float4 xv = sx4[idx];
            float4 hv = sh4[idx];
            acc += wv.x * xv.x + wv.y * xv.y + wv.z * xv.z + wv.w * xv.w;
            acc += uv.x * hv.x + uv.y * hv.y + uv.z * hv.z + uv.w * hv.w;
        }
    }
#pragma unroll
    for (int off = 16; off; off >>= 1)
        acc += __shfl_xor_sync(0xffffffffu, acc, off);

    if (lane == 0) sg[wib] = acc;
    __syncthreads();

    if (threadIdx.x < 2) {
        int un = blockIdx.x * 2 + threadIdx.x;
        float g0 = sg[0 + threadIdx.x];
        float g1 = sg[2 + threadIdx.x];
        float g2 = sg[4 + threadIdx.x];
        float g3 = sg[6 + threadIdx.x];
        if (mode == 4) {
            const float* pr = d_pre[tok_idx];
            g0 += pr[0 * HID + un];
            g1 += pr[1 * HID + un];
            g2 += pr[2 * HID + un];
            g3 += pr[3 * HID + un];
        }
        float gi = g0 + bih[0 * HID + un] + bhh[0 * HID + un];
        float gf = g1 + bih[1 * HID + un] + bhh[1 * HID + un];
        float gg = g2 + bih[2 * HID + un] + bhh[2 * HID + un];
        float go = g3 + bih[3 * HID + un] + bhh[3 * HID + un];
        float i_ = sigmoidf_(gi);
        float f_ = sigmoidf_(gf);
        float g_ = tanhf(gg);
        float o_ = sigmoidf_(go);
        float cn = f_ * d_c[layer][un] + i_ * g_;
        d_c[layer][un]          = cn;
        d_h[buf_out][layer][un] = o_ * tanhf(cn);
    }
}

// ---------------- logits + fused last-block finalize ----------------
__global__ void __launch_bounds__(256, 4)
logits_kernel(const float* __restrict__ W, const float* __restrict__ b,
              int buf_h)
{
    __shared__ float shv[HID];
    __shared__ float s[8];

    ((float4*)shv)[threadIdx.x] =
        ((const float4*)&d_h[buf_h][NL - 1][0])[threadIdx.x];
    __syncthreads();

    int wib  = threadIdx.x >> 5;
    int lane = threadIdx.x & 31;
    int row  = blockIdx.x * 8 + wib;

    const float4* h4 = (const float4*)shv;
    const float4* w4 = (const float4*)(W + (size_t)row * HID);

    float acc = 0.f;
#pragma unroll
    for (int i = 0; i < 8; i++) {
        int idx = i * 32 + lane;
        float4 wv = w4[idx];
        float4 hv = h4[idx];
        acc += wv.x * hv.x + wv.y * hv.y + wv.z * hv.z + wv.w * hv.w;
    }
#pragma unroll
    for (int off = 16; off; off >>= 1)
        acc += __shfl_xor_sync(0xffffffffu, acc, off);

    if (lane == 0) {
        acc += b[row];
        d_logits[row] = acc;
        s[wib] = acc;
    }
    __syncthreads();

    __shared__ int isLast;
    if (threadIdx.x == 0) {
        float m = s[0]; int mi = 0;
#pragma unroll
        for (int k = 1; k < 8; k++)
            if (s[k] > m) { m = s[k]; mi = k; }
        float sum = 0.f;
#pragma unroll
        for (int k = 0; k < 8; k++) sum += expf(s[k] - m);
        d_pmax[blockIdx.x] = m;
        d_psum[blockIdx.x] = sum;
        d_pidx[blockIdx.x] = blockIdx.x * 8 + mi;
        __threadfence();
        unsigned int c = atomicAdd(&d_count, 1u);
        isLast = (c == NB_LOGITS - 1) ? 1 : 0;
    }
    __syncthreads();
    if (!isLast) return;
    __threadfence();

    // ---- global finalize in the last block ----
    __shared__ float sm[256];
    __shared__ int   si[256];
    __shared__ float ss[256];
    int tid = threadIdx.x;

    float m = -3.0e38f; int mi = 0x7fffffff;
    for (int bk = tid; bk < NB_LOGITS; bk += 256) {
        float v = d_pmax[bk];
        int   ix = d_pidx[bk];
        if (v > m || (v == m && ix < mi)) { m = v; mi = ix; }
    }
    sm[tid] = m; si[tid] = mi;
    __syncthreads();
    for (int st = 128; st; st >>= 1) {
        if (tid < st) {
            if (sm[tid + st] > sm[tid] ||
                (sm[tid + st] == sm[tid] && si[tid + st] < si[tid])) {
                sm[tid] = sm[tid + st];
                si[tid] = si[tid + st];
            }
        }
        __syncthreads();
    }
    float M = sm[0];
    __syncthreads();

    float S = 0.f;
    for (int bk = tid; bk < NB_LOGITS; bk += 256)
        S += d_psum[bk] * expf(d_pmax[bk] - M);
    ss[tid] = S;
    __syncthreads();
    for (int st = 128; st; st >>= 1) {
        if (tid < st) ss[tid] += ss[tid + st];
        __syncthreads();
    }
    if (tid == 0) {
        d_M     = M;
        d_logS  = logf(ss[0]);
        d_token = si[0];
        d_count = 0u;
    }
}

// ---------------- trailing log-prob write (final decoder step) ----------------
__global__ void __launch_bounds__(256)
write_logp_kernel(float* __restrict__ out)
{
    int i = blockIdx.x * blockDim.x + threadIdx.x;
    if (i < VOCAB) out[i] = d_logits[i] - d_M - d_logS;
}

// ---------------- host orchestration ----------------
extern "C" void kernel_launch(void* const* d_in, const int* in_sizes, int n_in,
                              void* d_out, int out_size)
{
    (void)in_sizes; (void)n_in;
    const int*   src     = (const int*)  d_in[0];
    const float* emb_enc = (const float*)d_in[2];
    const float* enc_Wih = (const float*)d_in[3];
    const float* enc_Whh = (const float*)d_in[4];
    const float* enc_bih = (const float*)d_in[5];
    const float* enc_bhh = (const float*)d_in[6];
    const float* emb_dec = (const float*)d_in[7];
    const float* dec_Wih = (const float*)d_in[8];
    const float* dec_Whh = (const float*)d_in[9];
    const float* dec_bih = (const float*)d_in[10];
    const float* dec_bhh = (const float*)d_in[11];
    const float* out_W   = (const float*)d_in[12];
    const float* out_b   = (const float*)d_in[13];
    float* out = (float*)d_out;
    (void)out_size;

    const size_t WOFF = (size_t)4 * HID * HID;
    const size_t BOFF = (size_t)4 * HID;

    init_state_kernel<<<24, 256>>>();

    // encoder layer-0 input GEMM for all 64 tokens
    enc_pre_kernel<<<dim3(4 * HID / 8, SEQ / 8), 256>>>(enc_Wih, emb_enc, src);

    int p = 0;

    // ---- encoder ----
    for (int t = 0; t < SEQ; t++) {
        lstm_layer_kernel<<<HID / 2, 256>>>(
            nullptr, enc_Whh, enc_bih, enc_bhh,
            nullptr, nullptr, t, /*mode=*/4, p, 1 - p, /*layer=*/0);
        lstm_layer_kernel<<<HID / 2, 256>>>(
            enc_Wih + WOFF, enc_Whh + WOFF, enc_bih + BOFF, enc_bhh + BOFF,
            nullptr, nullptr, 0, /*mode=*/0, p, 1 - p, /*layer=*/1);
        p ^= 1;
    }

    // ---- decoder ----
    for (int t = 0; t < SEQ; t++) {
        int mode0 = (t == 0) ? 2 : 3;
        int tokix = (t == 0) ? BOS : 0;
        float* out_prev = (t == 0) ? nullptr : out + (size_t)(t - 1) * VOCAB;
        lstm_layer_kernel<<<HID / 2, 256>>>(
            dec_Wih, dec_Whh, dec_bih, dec_bhh,
            emb_dec, out_prev, tokix, mode0, p, 1 - p, /*layer=*/0);
        lstm_layer_kernel<<<HID / 2, 256>>>(
            dec_Wih + WOFF, dec_Whh + WOFF, dec_bih + BOFF, dec_bhh + BOFF,
            nullptr, nullptr, 0, /*mode=*/0, p, 1 - p, /*layer=*/1);

        logits_kernel<<<NB_LOGITS, 256>>>(out_W, out_b, 1 - p);
        p ^= 1;
    }

    write_logp_kernel<<<(VOCAB + 255) / 256, 256>>>(out + (size_t)(SEQ - 1) * VOCAB);
}

// round 4
// speedup vs baseline: 1.3214x; 1.0043x over previous
#include <cuda_runtime.h>
#include <cuda_bf16.h>
#include <math.h>

#define HID   1024
#define VOCAB 32000
#define SEQ   64
#define NL    2
#define BOS   1

// ---------------- device scratch ----------------
__device__ float d_h[2][NL][HID];
__device__ float d_c[NL][HID];
__device__ float d_logits[VOCAB];
__device__ float d_pre[SEQ][4 * HID];                 // encoder L0 Wih@x precompute
__device__ __nv_bfloat16 d_Wbf[(size_t)VOCAB * HID];  // bf16 copy of out_W (64 MB)
#define NB_LOGITS (VOCAB / 8)                          // 4000 blocks
__device__ float d_pmax[NB_LOGITS];
__device__ float d_psum[NB_LOGITS];
__device__ int   d_pidx[NB_LOGITS];
__device__ unsigned int d_count;
__device__ int   d_token;
__device__ float d_M, d_logS;

// ---------------- init ----------------
__global__ void init_state_kernel() {
    int i = blockIdx.x * blockDim.x + threadIdx.x;
    if (i < 2 * NL * HID) ((float*)d_h)[i] = 0.0f;
    if (i < NL * HID)     ((float*)d_c)[i] = 0.0f;
    if (i == 0)           d_count = 0u;
}

// ---------------- out_W fp32 -> bf16 conversion (once per launch) ----------------
__global__ void __launch_bounds__(256)
convert_w_kernel(const float* __restrict__ W)
{
    size_t i = (size_t)blockIdx.x * 256 + threadIdx.x;   // uint4 index: 8 elems
    const float4* w4 = (const float4*)W;
    float4 a = w4[2 * i];
    float4 b = w4[2 * i + 1];
    __nv_bfloat162 r[4];
    r[0] = __nv_bfloat162(__float2bfloat16(a.x), __float2bfloat16(a.y));
    r[1] = __nv_bfloat162(__float2bfloat16(a.z), __float2bfloat16(a.w));
    r[2] = __nv_bfloat162(__float2bfloat16(b.x), __float2bfloat16(b.y));
    r[3] = __nv_bfloat162(__float2bfloat16(b.z), __float2bfloat16(b.w));
    ((uint4*)d_Wbf)[i] = *(uint4*)r;
}

__device__ __forceinline__ float sigmoidf_(float x) {
    return 1.0f / (1.0f + expf(-x));
}

// ---------------- encoder layer-0 input GEMM ----------------
__global__ void __launch_bounds__(256, 4)
enc_pre_kernel(const float* __restrict__ Wih, const float* __restrict__ emb,
               const int* __restrict__ src)
{
    __shared__ float sx[8][HID];
    int tid = threadIdx.x;

    for (int j = 0; j < 8; j++) {
        int tok = src[blockIdx.y * 8 + j];
        ((float4*)sx[j])[tid] = ((const float4*)(emb + (size_t)tok * HID))[tid];
    }
    __syncthreads();

    int wib  = tid >> 5;
    int lane = tid & 31;
    int row  = blockIdx.x * 8 + wib;
    const float4* w4 = (const float4*)(Wih + (size_t)row * HID);

    float acc[8] = {0.f,0.f,0.f,0.f,0.f,0.f,0.f,0.f};
#pragma unroll
    for (int i = 0; i < 8; i++) {
        int idx = i * 32 + lane;
        float4 wv = w4[idx];
#pragma unroll
        for (int t = 0; t < 8; t++) {
            float4 xv = ((const float4*)sx[t])[idx];
            acc[t] += wv.x * xv.x + wv.y * xv.y + wv.z * xv.z + wv.w * xv.w;
        }
    }
#pragma unroll
    for (int off = 16; off; off >>= 1)
#pragma unroll
        for (int t = 0; t < 8; t++)
            acc[t] += __shfl_xor_sync(0xffffffffu, acc[t], off);

    if (lane == 0) {
#pragma unroll
        for (int t = 0; t < 8; t++)
            d_pre[blockIdx.y * 8 + t][row] = acc[t];
    }
}

// ---------------- fused LSTM layer step, split-K ----------------
// grid = HID blocks (one hidden unit each); 8 warps = 4 gates x 2 K-halves.
// mode: 0 = x from d_h[buf_out][0]; 2 = emb+tok_idx*H; 3 = emb+d_token*H;
//       4 = encoder L0: Wih@x taken from d_pre[tok_idx], only Whh dot here.
__global__ void __launch_bounds__(256, 4)
lstm_layer_kernel(const float* __restrict__ Wih, const float* __restrict__ Whh,
                  const float* __restrict__ bih, const float* __restrict__ bhh,
                  const float* __restrict__ emb, float* __restrict__ out_prev,
                  int tok_idx, int mode, int buf_in, int buf_out, int layer)
{
    if (out_prev) {
        int gid = blockIdx.x * blockDim.x + threadIdx.x;
        if (gid < VOCAB) out_prev[gid] = d_logits[gid] - d_M - d_logS;
    }

    __shared__ float sx[HID];
    __shared__ float sh[HID];
    __shared__ float sg[8];

    const float* h_in = &d_h[buf_in][layer][0];
    ((float4*)sh)[threadIdx.x] = ((const float4*)h_in)[threadIdx.x];

    if (mode != 4) {
        const float* x;
        if (mode == 0)      x = &d_h[buf_out][0][0];
        else if (mode == 2) x = emb + (size_t)tok_idx * HID;
        else                x = emb + (size_t)d_token * HID;
        ((float4*)sx)[threadIdx.x] = ((const float4*)x)[threadIdx.x];
    }
    __syncthreads();

    int wib  = threadIdx.x >> 5;
    int lane = threadIdx.x & 31;
    int half = wib & 1;            // K half: cols [half*512, half*512+512)
    int gate = wib >> 1;           // 0..3
    int unit = blockIdx.x;
    size_t row_off = (size_t)(gate * HID + unit) * HID;

    const float4* v4  = (const float4*)(Whh + row_off);
    const float4* sh4 = (const float4*)sh;
    int base = half * 128;         // float4 offset of this half

    float acc = 0.f;
    if (mode == 4) {
#pragma unroll
        for (int i = 0; i < 4; i++) {
            int idx = base + i * 32 + lane;
            float4 uv = v4[idx];
            float4 hv = sh4[idx];
            acc += uv.x * hv.x + uv.y * hv.y + uv.z * hv.z + uv.w * hv.w;
        }
    } else {
        const float4* w4  = (const float4*)(Wih + row_off);
        const float4* sx4 = (const float4*)sx;
#pragma unroll
        for (int i = 0; i < 4; i++) {
            int idx = base + i * 32 + lane;
            float4 wv = w4[idx];
            float4 uv = v4[idx];
            float4 xv = sx4[idx];
            float4 hv = sh4[idx];
            acc += wv.x * xv.x + wv.y * xv.y + wv.z * xv.z + wv.w * xv.w;
            acc += uv.x * hv.x + uv.y * hv.y + uv.z * hv.z + uv.w * hv.w;
        }
    }
#pragma unroll
    for (int off = 16; off; off >>= 1)
        acc += __shfl_xor_sync(0xffffffffu, acc, off);

    if (lane == 0) sg[wib] = acc;
    __syncthreads();

    if (threadIdx.x == 0) {
        int un = unit;
        float g0 = sg[0] + sg[1];
        float g1 = sg[2] + sg[3];
        float g2 = sg[4] + sg[5];
        float g3 = sg[6] + sg[7];
        if (mode == 4) {
            const float* pr = d_pre[tok_idx];
            g0 += pr[0 * HID + un];
            g1 += pr[1 * HID + un];
            g2 += pr[2 * HID + un];
            g3 += pr[3 * HID + un];
        }
        float gi = g0 + bih[0 * HID + un] + bhh[0 * HID + un];
        float gf = g1 + bih[1 * HID + un] + bhh[1 * HID + un];
        float gg = g2 + bih[2 * HID + un] + bhh[2 * HID + un];
        float go = g3 + bih[3 * HID + un] + bhh[3 * HID + un];
        float i_ = sigmoidf_(gi);
        float f_ = sigmoidf_(gf);
        float g_ = tanhf(gg);
        float o_ = sigmoidf_(go);
        float cn = f_ * d_c[layer][un] + i_ * g_;
        d_c[layer][un]          = cn;
        d_h[buf_out][layer][un] = o_ * tanhf(cn);
    }
}

// ---------------- logits (bf16 W) + fused last-block finalize ----------------
__global__ void __launch_bounds__(256, 4)
logits_kernel(const float* __restrict__ b, int buf_h)
{
    __shared__ float sht[8][128];   // transposed h: sht[c&7][c>>3] = h[c]
    __shared__ float s[8];

    {
        float4 v = ((const float4*)&d_h[buf_h][NL - 1][0])[threadIdx.x];
        int c = threadIdx.x * 4;
        sht[(c + 0) & 7][(c + 0) >> 3] = v.x;
        sht[(c + 1) & 7][(c + 1) >> 3] = v.y;
        sht[(c + 2) & 7][(c + 2) >> 3] = v.z;
        sht[(c + 3) & 7][(c + 3) >> 3] = v.w;
    }
    __syncthreads();

    int wib  = threadIdx.x >> 5;
    int lane = threadIdx.x & 31;
    int row  = blockIdx.x * 8 + wib;

    const uint4* w4 = (const uint4*)(d_Wbf + (size_t)row * HID);

    float acc = 0.f;
#pragma unroll
    for (int i = 0; i < 4; i++) {
        int idx = i * 32 + lane;
        uint4 wv = w4[idx];
        __nv_bfloat162* p = (__nv_bfloat162*)&wv;
#pragma unroll
        for (int k = 0; k < 4; k++) {
            float2 f = __bfloat1622float2(p[k]);
            acc += f.x * sht[2 * k][idx] + f.y * sht[2 * k + 1][idx];
        }
    }
#pragma unroll
    for (int off = 16; off; off >>= 1)
        acc += __shfl_xor_sync(0xffffffffu, acc, off);

    if (lane == 0) {
        acc += b[row];
        d_logits[row] = acc;
        s[wib] = acc;
    }
    __syncthreads();

    __shared__ int isLast;
    if (threadIdx.x == 0) {
        float m = s[0]; int mi = 0;
#pragma unroll
        for (int k = 1; k < 8; k++)
            if (s[k] > m) { m = s[k]; mi = k; }
        float sum = 0.f;
#pragma unroll
        for (int k = 0; k < 8; k++) sum += expf(s[k] - m);
        d_pmax[blockIdx.x] = m;
        d_psum[blockIdx.x] = sum;
        d_pidx[blockIdx.x] = blockIdx.x * 8 + mi;
        __threadfence();
        unsigned int c = atomicAdd(&d_count, 1u);
        isLast = (c == NB_LOGITS - 1) ? 1 : 0;
    }
    __syncthreads();
    if (!isLast) return;
    __threadfence();

    __shared__ float sm[256];
    __shared__ int   si[256];
    __shared__ float ss[256];
    int tid = threadIdx.x;

    float m = -3.0e38f; int mi = 0x7fffffff;
    for (int bk = tid; bk < NB_LOGITS; bk += 256) {
        float v = d_pmax[bk];
        int   ix = d_pidx[bk];
        if (v > m || (v == m && ix < mi)) { m = v; mi = ix; }
    }
    sm[tid] = m; si[tid] = mi;
    __syncthreads();
    for (int st = 128; st; st >>= 1) {
        if (tid < st) {
            if (sm[tid + st] > sm[tid] ||
                (sm[tid + st] == sm[tid] && si[tid + st] < si[tid])) {
                sm[tid] = sm[tid + st];
                si[tid] = si[tid + st];
            }
        }
        __syncthreads();
    }
    float M = sm[0];
    __syncthreads();

    float S = 0.f;
    for (int bk = tid; bk < NB_LOGITS; bk += 256)
        S += d_psum[bk] * expf(d_pmax[bk] - M);
    ss[tid] = S;
    __syncthreads();
    for (int st = 128; st; st >>= 1) {
        if (tid < st) ss[tid] += ss[tid + st];
        __syncthreads();
    }
    if (tid == 0) {
        d_M     = M;
        d_logS  = logf(ss[0]);
        d_token = si[0];
        d_count = 0u;
    }
}

// ---------------- trailing log-prob write ----------------
__global__ void __launch_bounds__(256)
write_logp_kernel(float* __restrict__ out)
{
    int i = blockIdx.x * blockDim.x + threadIdx.x;
    if (i < VOCAB) out[i] = d_logits[i] - d_M - d_logS;
}

// ---------------- host orchestration ----------------
extern "C" void kernel_launch(void* const* d_in, const int* in_sizes, int n_in,
                              void* d_out, int out_size)
{
    (void)in_sizes; (void)n_in;
    const int*   src     = (const int*)  d_in[0];
    const float* emb_enc = (const float*)d_in[2];
    const float* enc_Wih = (const float*)d_in[3];
    const float* enc_Whh = (const float*)d_in[4];
    const float* enc_bih = (const float*)d_in[5];
    const float* enc_bhh = (const float*)d_in[6];
    const float* emb_dec = (const float*)d_in[7];
    const float* dec_Wih = (const float*)d_in[8];
    const float* dec_Whh = (const float*)d_in[9];
    const float* dec_bih = (const float*)d_in[10];
    const float* dec_bhh = (const float*)d_in[11];
    const float* out_W   = (const float*)d_in[12];
    const float* out_b   = (const float*)d_in[13];
    float* out = (float*)d_out;
    (void)out_size;

    const size_t WOFF = (size_t)4 * HID * HID;
    const size_t BOFF = (size_t)4 * HID;

    init_state_kernel<<<24, 256>>>();
    convert_w_kernel<<<(int)((size_t)VOCAB * HID / 8 / 256), 256>>>(out_W);
    enc_pre_kernel<<<dim3(4 * HID / 8, SEQ / 8), 256>>>(enc_Wih, emb_enc, src);

    int p = 0;

    // ---- encoder ----
    for (int t = 0; t < SEQ; t++) {
        lstm_layer_kernel<<<HID, 256>>>(
            nullptr, enc_Whh, enc_bih, enc_bhh,
            nullptr, nullptr, t, /*mode=*/4, p, 1 - p, /*layer=*/0);
        lstm_layer_kernel<<<HID, 256>>>(
            enc_Wih + WOFF, enc_Whh + WOFF, enc_bih + BOFF, enc_bhh + BOFF,
            nullptr, nullptr, 0, /*mode=*/0, p, 1 - p, /*layer=*/1);
        p ^= 1;
    }

    // ---- decoder ----
    for (int t = 0; t < SEQ; t++) {
        int mode0 = (t == 0) ? 2 : 3;
        int tokix = (t == 0) ? BOS : 0;
        float* out_prev = (t == 0) ? nullptr : out + (size_t)(t - 1) * VOCAB;
        lstm_layer_kernel<<<HID, 256>>>(
            dec_Wih, dec_Whh, dec_bih, dec_bhh,
            emb_dec, out_prev, tokix, mode0, p, 1 - p, /*layer=*/0);
        lstm_layer_kernel<<<HID, 256>>>(
            dec_Wih + WOFF, dec_Whh + WOFF, dec_bih + BOFF, dec_bhh + BOFF,
            nullptr, nullptr, 0, /*mode=*/0, p, 1 - p, /*layer=*/1);

        logits_kernel<<<NB_LOGITS, 256>>>(out_b, 1 - p);
        p ^= 1;
    }

    write_logp_kernel<<<(VOCAB + 255) / 256, 256>>>(out + (size_t)(SEQ - 1) * VOCAB);
}

// round 5
// speedup vs baseline: 1.6675x; 1.2619x over previous
#include <cuda_runtime.h>
#include <cuda_bf16.h>
#include <math.h>

#define HID   1024
#define VOCAB 32000
#define SEQ   64
#define NL    2
#define BOS   1

// ---------------- device scratch ----------------
__device__ float d_h[2][NL][HID];
__device__ float d_c[NL][HID];
__device__ float d_logits[VOCAB];
__device__ float d_pre[SEQ][4 * HID];                 // encoder L0 Wih@x precompute
__device__ __nv_bfloat16 d_Wbf[(size_t)VOCAB * HID];  // bf16 out_W (65.5 MB)
// bf16 LSTM weights: 0=enc_Whh0 1=enc_Wih1 2=enc_Whh1 3=dec_Wih0 4=dec_Whh0 5=dec_Wih1 6=dec_Whh1
__device__ __nv_bfloat16 d_Lbf[7][(size_t)4 * HID * HID];
#define NB_LOGITS (VOCAB / 8)                          // 4000 blocks
__device__ float d_pmax[NB_LOGITS];
__device__ float d_psum[NB_LOGITS];
__device__ int   d_pidx[NB_LOGITS];
__device__ unsigned int d_count;
__device__ int   d_token;
__device__ float d_M, d_logS;

// ---------------- init ----------------
__global__ void init_state_kernel() {
    int i = blockIdx.x * blockDim.x + threadIdx.x;
    if (i < 2 * NL * HID) ((float*)d_h)[i] = 0.0f;
    if (i < NL * HID)     ((float*)d_c)[i] = 0.0f;
    if (i == 0)           d_count = 0u;
}

// ---------------- fp32 -> bf16 converters ----------------
__device__ __forceinline__ uint4 cvt8(const float4 a, const float4 b) {
    __nv_bfloat162 r[4];
    r[0] = __nv_bfloat162(__float2bfloat16(a.x), __float2bfloat16(a.y));
    r[1] = __nv_bfloat162(__float2bfloat16(a.z), __float2bfloat16(a.w));
    r[2] = __nv_bfloat162(__float2bfloat16(b.x), __float2bfloat16(b.y));
    r[3] = __nv_bfloat162(__float2bfloat16(b.z), __float2bfloat16(b.w));
    return *(uint4*)r;
}

__global__ void __launch_bounds__(256)
convert_w_kernel(const float* __restrict__ W)
{
    size_t i = (size_t)blockIdx.x * 256 + threadIdx.x;   // uint4 index: 8 elems
    const float4* w4 = (const float4*)W;
    ((uint4*)d_Wbf)[i] = cvt8(w4[2 * i], w4[2 * i + 1]);
}

// grid (2048, 7): converts the 7 LSTM matrices
__global__ void __launch_bounds__(256)
convert_lstm_kernel(const float* __restrict__ eWih, const float* __restrict__ eWhh,
                    const float* __restrict__ dWih, const float* __restrict__ dWhh)
{
    const size_t WOFF = (size_t)4 * HID * HID;
    int m = blockIdx.y;
    const float* src;
    switch (m) {
        case 0: src = eWhh;        break;
        case 1: src = eWih + WOFF; break;
        case 2: src = eWhh + WOFF; break;
        case 3: src = dWih;        break;
        case 4: src = dWhh;        break;
        case 5: src = dWih + WOFF; break;
        default: src = dWhh + WOFF; break;
    }
    size_t i = (size_t)blockIdx.x * 256 + threadIdx.x;
    const float4* s4 = (const float4*)src;
    ((uint4*)d_Lbf[m])[i] = cvt8(s4[2 * i], s4[2 * i + 1]);
}

__device__ __forceinline__ float sigmoidf_(float x) {
    return 1.0f / (1.0f + expf(-x));
}

// ---------------- encoder layer-0 input GEMM (fp32, once) ----------------
__global__ void __launch_bounds__(256, 4)
enc_pre_kernel(const float* __restrict__ Wih, const float* __restrict__ emb,
               const int* __restrict__ src)
{
    __shared__ float sx[8][HID];
    int tid = threadIdx.x;

    for (int j = 0; j < 8; j++) {
        int tok = src[blockIdx.y * 8 + j];
        ((float4*)sx[j])[tid] = ((const float4*)(emb + (size_t)tok * HID))[tid];
    }
    __syncthreads();

    int wib  = tid >> 5;
    int lane = tid & 31;
    int row  = blockIdx.x * 8 + wib;
    const float4* w4 = (const float4*)(Wih + (size_t)row * HID);

    float acc[8] = {0.f,0.f,0.f,0.f,0.f,0.f,0.f,0.f};
#pragma unroll
    for (int i = 0; i < 8; i++) {
        int idx = i * 32 + lane;
        float4 wv = w4[idx];
#pragma unroll
        for (int t = 0; t < 8; t++) {
            float4 xv = ((const float4*)sx[t])[idx];
            acc[t] += wv.x * xv.x + wv.y * xv.y + wv.z * xv.z + wv.w * xv.w;
        }
    }
#pragma unroll
    for (int off = 16; off; off >>= 1)
#pragma unroll
        for (int t = 0; t < 8; t++)
            acc[t] += __shfl_xor_sync(0xffffffffu, acc[t], off);

    if (lane == 0) {
#pragma unroll
        for (int t = 0; t < 8; t++)
            d_pre[blockIdx.y * 8 + t][row] = acc[t];
    }
}

// ---------------- fused LSTM layer step, bf16 weights ----------------
// grid = HID/2 blocks (2 units each); 8 warps = 4 gates x 2 units; warp = 1 gate row.
// wih_idx / whh_idx select matrices in d_Lbf (wih_idx = -1 in mode 4).
// mode: 0 = x from d_h[buf_out][0]; 2 = emb+tok_idx*H; 3 = emb+d_token*H;
//       4 = encoder L0: Wih@x taken from d_pre[tok_idx], only Whh dot here.
__global__ void __launch_bounds__(256, 4)
lstm_layer_kernel(int wih_idx, int whh_idx,
                  const float* __restrict__ bih, const float* __restrict__ bhh,
                  const float* __restrict__ emb, float* __restrict__ out_prev,
                  int tok_idx, int mode, int buf_in, int buf_out, int layer)
{
    if (out_prev) {
        int gid = blockIdx.x * blockDim.x + threadIdx.x;
        if (gid < VOCAB) out_prev[gid] = d_logits[gid] - d_M - d_logS;
    }

    __shared__ float sxt[8][128];   // transposed x: col c -> sxt[c&7][c>>3]
    __shared__ float sht[8][128];   // transposed h
    __shared__ float sg[8];

    {
        float4 v = ((const float4*)&d_h[buf_in][layer][0])[threadIdx.x];
        int c = threadIdx.x * 4;
        sht[(c + 0) & 7][(c + 0) >> 3] = v.x;
        sht[(c + 1) & 7][(c + 1) >> 3] = v.y;
        sht[(c + 2) & 7][(c + 2) >> 3] = v.z;
        sht[(c + 3) & 7][(c + 3) >> 3] = v.w;
    }
    if (mode != 4) {
        const float* x;
        if (mode == 0)      x = &d_h[buf_out][0][0];
        else if (mode == 2) x = emb + (size_t)tok_idx * HID;
        else                x = emb + (size_t)d_token * HID;
        float4 v = ((const float4*)x)[threadIdx.x];
        int c = threadIdx.x * 4;
        sxt[(c + 0) & 7][(c + 0) >> 3] = v.x;
        sxt[(c + 1) & 7][(c + 1) >> 3] = v.y;
        sxt[(c + 2) & 7][(c + 2) >> 3] = v.z;
        sxt[(c + 3) & 7][(c + 3) >> 3] = v.w;
    }
    __syncthreads();

    int wib  = threadIdx.x >> 5;
    int lane = threadIdx.x & 31;
    int u    = wib & 1;
    int gate = wib >> 1;
    int unit = blockIdx.x * 2 + u;
    size_t row_off = (size_t)(gate * HID + unit) * HID;   // element offset

    const uint4* v4 = (const uint4*)(d_Lbf[whh_idx] + row_off);  // 128 uint4/row

    float acc = 0.f;
    if (mode == 4) {
#pragma unroll
        for (int i = 0; i < 4; i++) {
            int idx = i * 32 + lane;
            uint4 wv = v4[idx];
            __nv_bfloat162* p = (__nv_bfloat162*)&wv;
#pragma unroll
            for (int k = 0; k < 4; k++) {
                float2 f = __bfloat1622float2(p[k]);
                acc += f.x * sht[2 * k][idx] + f.y * sht[2 * k + 1][idx];
            }
        }
    } else {
        const uint4* w4 = (const uint4*)(d_Lbf[wih_idx] + row_off);
#pragma unroll
        for (int i = 0; i < 4; i++) {
            int idx = i * 32 + lane;
            uint4 wv = w4[idx];
            uint4 uv = v4[idx];
            __nv_bfloat162* pw = (__nv_bfloat162*)&wv;
            __nv_bfloat162* pu = (__nv_bfloat162*)&uv;
#pragma unroll
            for (int k = 0; k < 4; k++) {
                float2 fw = __bfloat1622float2(pw[k]);
                float2 fu = __bfloat1622float2(pu[k]);
                acc += fw.x * sxt[2 * k][idx] + fw.y * sxt[2 * k + 1][idx];
                acc += fu.x * sht[2 * k][idx] + fu.y * sht[2 * k + 1][idx];
            }
        }
    }
#pragma unroll
    for (int off = 16; off; off >>= 1)
        acc += __shfl_xor_sync(0xffffffffu, acc, off);

    if (lane == 0) sg[wib] = acc;
    __syncthreads();

    if (threadIdx.x < 2) {
        int un = blockIdx.x * 2 + threadIdx.x;
        float g0 = sg[0 + threadIdx.x];
        float g1 = sg[2 + threadIdx.x];
        float g2 = sg[4 + threadIdx.x];
        float g3 = sg[6 + threadIdx.x];
        if (mode == 4) {
            const float* pr = d_pre[tok_idx];
            g0 += pr[0 * HID + un];
            g1 += pr[1 * HID + un];
            g2 += pr[2 * HID + un];
            g3 += pr[3 * HID + un];
        }
        float gi = g0 + bih[0 * HID + un] + bhh[0 * HID + un];
        float gf = g1 + bih[1 * HID + un] + bhh[1 * HID + un];
        float gg = g2 + bih[2 * HID + un] + bhh[2 * HID + un];
        float go = g3 + bih[3 * HID + un] + bhh[3 * HID + un];
        float i_ = sigmoidf_(gi);
        float f_ = sigmoidf_(gf);
        float g_ = tanhf(gg);
        float o_ = sigmoidf_(go);
        float cn = f_ * d_c[layer][un] + i_ * g_;
        d_c[layer][un]          = cn;
        d_h[buf_out][layer][un] = o_ * tanhf(cn);
    }
}

// ---------------- logits (bf16 W) + fused last-block finalize ----------------
__global__ void __launch_bounds__(256, 4)
logits_kernel(const float* __restrict__ b, int buf_h)
{
    __shared__ float sht[8][128];
    __shared__ float s[8];

    {
        float4 v = ((const float4*)&d_h[buf_h][NL - 1][0])[threadIdx.x];
        int c = threadIdx.x * 4;
        sht[(c + 0) & 7][(c + 0) >> 3] = v.x;
        sht[(c + 1) & 7][(c + 1) >> 3] = v.y;
        sht[(c + 2) & 7][(c + 2) >> 3] = v.z;
        sht[(c + 3) & 7][(c + 3) >> 3] = v.w;
    }
    __syncthreads();

    int wib  = threadIdx.x >> 5;
    int lane = threadIdx.x & 31;
    int row  = blockIdx.x * 8 + wib;

    const uint4* w4 = (const uint4*)(d_Wbf + (size_t)row * HID);

    float acc = 0.f;
#pragma unroll
    for (int i = 0; i < 4; i++) {
        int idx = i * 32 + lane;
        uint4 wv = w4[idx];
        __nv_bfloat162* p = (__nv_bfloat162*)&wv;
#pragma unroll
        for (int k = 0; k < 4; k++) {
            float2 f = __bfloat1622float2(p[k]);
            acc += f.x * sht[2 * k][idx] + f.y * sht[2 * k + 1][idx];
        }
    }
#pragma unroll
    for (int off = 16; off; off >>= 1)
        acc += __shfl_xor_sync(0xffffffffu, acc, off);

    if (lane == 0) {
        acc += b[row];
        d_logits[row] = acc;
        s[wib] = acc;
    }
    __syncthreads();

    __shared__ int isLast;
    if (threadIdx.x == 0) {
        float m = s[0]; int mi = 0;
#pragma unroll
        for (int k = 1; k < 8; k++)
            if (s[k] > m) { m = s[k]; mi = k; }
        float sum = 0.f;
#pragma unroll
        for (int k = 0; k < 8; k++) sum += expf(s[k] - m);
        d_pmax[blockIdx.x] = m;
        d_psum[blockIdx.x] = sum;
        d_pidx[blockIdx.x] = blockIdx.x * 8 + mi;
        __threadfence();
        unsigned int c = atomicAdd(&d_count, 1u);
        isLast = (c == NB_LOGITS - 1) ? 1 : 0;
    }
    __syncthreads();
    if (!isLast) return;
    __threadfence();

    __shared__ float sm[256];
    __shared__ int   si[256];
    __shared__ float ss[256];
    int tid = threadIdx.x;

    float m = -3.0e38f; int mi = 0x7fffffff;
    for (int bk = tid; bk < NB_LOGITS; bk += 256) {
        float v = d_pmax[bk];
        int   ix = d_pidx[bk];
        if (v > m || (v == m && ix < mi)) { m = v; mi = ix; }
    }
    sm[tid] = m; si[tid] = mi;
    __syncthreads();
    for (int st = 128; st; st >>= 1) {
        if (tid < st) {
            if (sm[tid + st] > sm[tid] ||
                (sm[tid + st] == sm[tid] && si[tid + st] < si[tid])) {
                sm[tid] = sm[tid + st];
                si[tid] = si[tid + st];
            }
        }
        __syncthreads();
    }
    float M = sm[0];
    __syncthreads();

    float S = 0.f;
    for (int bk = tid; bk < NB_LOGITS; bk += 256)
        S += d_psum[bk] * expf(d_pmax[bk] - M);
    ss[tid] = S;
    __syncthreads();
    for (int st = 128; st; st >>= 1) {
        if (tid < st) ss[tid] += ss[tid + st];
        __syncthreads();
    }
    if (tid == 0) {
        d_M     = M;
        d_logS  = logf(ss[0]);
        d_token = si[0];
        d_count = 0u;
    }
}

// ---------------- trailing log-prob write ----------------
__global__ void __launch_bounds__(256)
write_logp_kernel(float* __restrict__ out)
{
    int i = blockIdx.x * blockDim.x + threadIdx.x;
    if (i < VOCAB) out[i] = d_logits[i] - d_M - d_logS;
}

// ---------------- host orchestration ----------------
extern "C" void kernel_launch(void* const* d_in, const int* in_sizes, int n_in,
                              void* d_out, int out_size)
{
    (void)in_sizes; (void)n_in;
    const int*   src     = (const int*)  d_in[0];
    const float* emb_enc = (const float*)d_in[2];
    const float* enc_Wih = (const float*)d_in[3];
    const float* enc_Whh = (const float*)d_in[4];
    const float* enc_bih = (const float*)d_in[5];
    const float* enc_bhh = (const float*)d_in[6];
    const float* emb_dec = (const float*)d_in[7];
    const float* dec_Wih = (const float*)d_in[8];
    const float* dec_Whh = (const float*)d_in[9];
    const float* dec_bih = (const float*)d_in[10];
    const float* dec_bhh = (const float*)d_in[11];
    const float* out_W   = (const float*)d_in[12];
    const float* out_b   = (const float*)d_in[13];
    float* out = (float*)d_out;
    (void)out_size;

    const size_t BOFF = (size_t)4 * HID;

    init_state_kernel<<<24, 256>>>();
    convert_w_kernel<<<(int)((size_t)VOCAB * HID / 8 / 256), 256>>>(out_W);
    convert_lstm_kernel<<<dim3(2048, 7), 256>>>(enc_Wih, enc_Whh, dec_Wih, dec_Whh);
    enc_pre_kernel<<<dim3(4 * HID / 8, SEQ / 8), 256>>>(enc_Wih, emb_enc, src);

    int p = 0;

    // ---- encoder ----
    for (int t = 0; t < SEQ; t++) {
        lstm_layer_kernel<<<HID / 2, 256>>>(
            -1, 0, enc_bih, enc_bhh,
            nullptr, nullptr, t, /*mode=*/4, p, 1 - p, /*layer=*/0);
        lstm_layer_kernel<<<HID / 2, 256>>>(
            1, 2, enc_bih + BOFF, enc_bhh + BOFF,
            nullptr, nullptr, 0, /*mode=*/0, p, 1 - p, /*layer=*/1);
        p ^= 1;
    }

    // ---- decoder ----
    for (int t = 0; t < SEQ; t++) {
        int mode0 = (t == 0) ? 2 : 3;
        int tokix = (t == 0) ? BOS : 0;
        float* out_prev = (t == 0) ? nullptr : out + (size_t)(t - 1) * VOCAB;
        lstm_layer_kernel<<<HID / 2, 256>>>(
            3, 4, dec_bih, dec_bhh,
            emb_dec, out_prev, tokix, mode0, p, 1 - p, /*layer=*/0);
        lstm_layer_kernel<<<HID / 2, 256>>>(
            5, 6, dec_bih + BOFF, dec_bhh + BOFF,
            nullptr, nullptr, 0, /*mode=*/0, p, 1 - p, /*layer=*/1);

        logits_kernel<<<NB_LOGITS, 256>>>(out_b, 1 - p);
        p ^= 1;
    }

    write_logp_kernel<<<(VOCAB + 255) / 256, 256>>>(out + (size_t)(SEQ - 1) * VOCAB);
}

// round 6
// speedup vs baseline: 2.0363x; 1.2211x over previous
#include <cuda_runtime.h>
#include <cuda_bf16.h>
#include <math.h>

#define HID   1024
#define VOCAB 32000
#define SEQ   64
#define NL    2
#define BOS   1
#define GRID  512
#define NT    256

// ---------------- device scratch ----------------
__device__ float d_h[2][NL][HID];                      // double-buffered h
__device__ float d_logits[VOCAB];
__device__ __nv_bfloat16 d_Wbf[(size_t)VOCAB * HID];   // bf16 out_W
// 0=eWih0 1=eWhh0 2=eWih1 3=eWhh1 4=dWih0 5=dWhh0 6=dWih1 7=dWhh1
__device__ __nv_bfloat16 d_Lbf[8][(size_t)4 * HID * HID];
__device__ float d_pmax[GRID];
__device__ float d_psum[GRID];
__device__ int   d_pidx[GRID];
__device__ unsigned int d_count = 0;
__device__ int   d_token;
__device__ float d_M, d_logS;
__device__ unsigned int g_gen = 0;
__device__ unsigned int g_cnt = 0;

// ---------------- fp32 -> bf16 converters ----------------
__device__ __forceinline__ uint4 cvt8(const float4 a, const float4 b) {
    __nv_bfloat162 r[4];
    r[0] = __nv_bfloat162(__float2bfloat16(a.x), __float2bfloat16(a.y));
    r[1] = __nv_bfloat162(__float2bfloat16(a.z), __float2bfloat16(a.w));
    r[2] = __nv_bfloat162(__float2bfloat16(b.x), __float2bfloat16(b.y));
    r[3] = __nv_bfloat162(__float2bfloat16(b.z), __float2bfloat16(b.w));
    return *(uint4*)r;
}

__global__ void __launch_bounds__(256)
convert_w_kernel(const float* __restrict__ W)
{
    size_t i = (size_t)blockIdx.x * 256 + threadIdx.x;
    const float4* w4 = (const float4*)W;
    ((uint4*)d_Wbf)[i] = cvt8(w4[2 * i], w4[2 * i + 1]);
}

// grid (2048, 8)
__global__ void __launch_bounds__(256)
convert_lstm_kernel(const float* __restrict__ eWih, const float* __restrict__ eWhh,
                    const float* __restrict__ dWih, const float* __restrict__ dWhh)
{
    const size_t WOFF = (size_t)4 * HID * HID;
    int m = blockIdx.y;
    const float* src;
    switch (m) {
        case 0: src = eWih;        break;
        case 1: src = eWhh;        break;
        case 2: src = eWih + WOFF; break;
        case 3: src = eWhh + WOFF; break;
        case 4: src = dWih;        break;
        case 5: src = dWhh;        break;
        case 6: src = dWih + WOFF; break;
        default: src = dWhh + WOFF; break;
    }
    size_t i = (size_t)blockIdx.x * 256 + threadIdx.x;
    const float4* s4 = (const float4*)src;
    ((uint4*)d_Lbf[m])[i] = cvt8(s4[2 * i], s4[2 * i + 1]);
}

// ---------------- helpers ----------------
__device__ __forceinline__ float sigmoidf_(float x) {
    return 1.0f / (1.0f + expf(-x));
}

// software grid barrier (all GRID blocks guaranteed co-resident)
__device__ __forceinline__ void gsync() {
    __syncthreads();
    if (threadIdx.x == 0) {
        __threadfence();
        unsigned int gen = *(volatile unsigned int*)&g_gen;
        if (atomicAdd(&g_cnt, 1u) == GRID - 1) {
            *(volatile unsigned int*)&g_cnt = 0u;
            __threadfence();
            *(volatile unsigned int*)&g_gen = gen + 1;
        } else {
            while (*(volatile unsigned int*)&g_gen == gen) __nanosleep(32);
            __threadfence();
        }
    }
    __syncthreads();
}

// stage fp32 vector (L2-coherent read) into conflict-free transposed smem
__device__ __forceinline__ void stage_T(float (*dst)[128], const float* src) {
    float4 v = __ldcg(((const float4*)src) + threadIdx.x);
    int c = threadIdx.x * 4;
    dst[(c + 0) & 7][(c + 0) >> 3] = v.x;
    dst[(c + 1) & 7][(c + 1) >> 3] = v.y;
    dst[(c + 2) & 7][(c + 2) >> 3] = v.z;
    dst[(c + 3) & 7][(c + 3) >> 3] = v.w;
}

__device__ __forceinline__ float dot_bf16(const __nv_bfloat16* Wr,
                                          const float (*sv)[128], int lane)
{
    const uint4* w4 = (const uint4*)Wr;
    float acc = 0.f;
#pragma unroll
    for (int i = 0; i < 4; i++) {
        int idx = i * 32 + lane;
        uint4 wv = w4[idx];
        __nv_bfloat162* p = (__nv_bfloat162*)&wv;
#pragma unroll
        for (int k = 0; k < 4; k++) {
            float2 f = __bfloat1622float2(p[k]);
            acc += f.x * sv[2 * k][idx] + f.y * sv[2 * k + 1][idx];
        }
    }
    return acc;
}

__device__ __forceinline__ float dot2_bf16(const __nv_bfloat16* Wr, const __nv_bfloat16* Ur,
                                           const float (*sx)[128], const float (*sh)[128],
                                           int lane)
{
    const uint4* w4 = (const uint4*)Wr;
    const uint4* u4 = (const uint4*)Ur;
    float acc = 0.f;
#pragma unroll
    for (int i = 0; i < 4; i++) {
        int idx = i * 32 + lane;
        uint4 wv = w4[idx];
        uint4 uv = u4[idx];
        __nv_bfloat162* pw = (__nv_bfloat162*)&wv;
        __nv_bfloat162* pu = (__nv_bfloat162*)&uv;
#pragma unroll
        for (int k = 0; k < 4; k++) {
            float2 fw = __bfloat1622float2(pw[k]);
            float2 fu = __bfloat1622float2(pu[k]);
            acc += fw.x * sx[2 * k][idx] + fw.y * sx[2 * k + 1][idx];
            acc += fu.x * sh[2 * k][idx] + fu.y * sh[2 * k + 1][idx];
        }
    }
    return acc;
}

__device__ __forceinline__ float warp_sum(float v) {
#pragma unroll
    for (int off = 16; off; off >>= 1)
        v += __shfl_xor_sync(0xffffffffu, v, off);
    return v;
}

// merge (m1,s1,i1) <- (m2,s2,i2) for online logsumexp+argmax (ties -> lower idx)
__device__ __forceinline__ void lse_merge(float& m1, float& s1, int& i1,
                                          float m2, float s2, int i2)
{
    if (m2 > m1)      { s1 = s1 * expf(m1 - m2) + s2; m1 = m2; i1 = i2; }
    else if (m2 == m1){ s1 += s2; if (i2 < i1) i1 = i2; }
    else              { s1 += s2 * expf(m2 - m1); }
}

// ---------------- persistent seq2seq kernel ----------------
__global__ void __launch_bounds__(NT, 4)
seq2seq_kernel(const int* __restrict__ src,
               const float* __restrict__ emb_enc,
               const float* __restrict__ enc_bih, const float* __restrict__ enc_bhh,
               const float* __restrict__ emb_dec,
               const float* __restrict__ dec_bih, const float* __restrict__ dec_bhh,
               const float* __restrict__ out_b,
               float* __restrict__ out)
{
    __shared__ float sxt[8][128];
    __shared__ float sht[8][128];
    __shared__ float sg[8];
    __shared__ float sc[NL][2];          // per-block cell state (units 2b, 2b+1)
    __shared__ float swm[8], sws[8];
    __shared__ int   swi[8];
    __shared__ float fm[NT], fs[NT];
    __shared__ int   fi[NT];
    __shared__ int   sflag;

    const int tid  = threadIdx.x;
    const int wib  = tid >> 5;
    const int lane = tid & 31;
    const int bx   = blockIdx.x;

    // ---- init state ----
    {
        int gid = bx * NT + tid;
        if (gid < 2 * NL * HID) ((float*)d_h)[gid] = 0.0f;
        if (tid < 2) { sc[0][tid] = 0.0f; sc[1][tid] = 0.0f; }
    }
    gsync();

    const int u    = wib & 1;
    const int gate = wib >> 1;
    const int unit = bx * 2 + u;
    const size_t row_off = (size_t)(gate * HID + unit) * HID;
    const size_t BOFF = (size_t)4 * HID;

    int p = 0;

    // ================= encoder + decoder =================
    for (int step = 0; step < 2 * SEQ; step++) {
        const bool dec = (step >= SEQ);
        const int  t   = dec ? step - SEQ : step;

        // ---------- layer 0 ----------
        const float* x0;
        if (!dec) {
            x0 = emb_enc + (size_t)src[t] * HID;
        } else {
            // write previous step's log-probs (d_logits/M/logS from last finalize)
            if (t > 0) {
                int gid = bx * NT + tid;
                if (gid < VOCAB)
                    out[(size_t)(t - 1) * VOCAB + gid] =
                        __ldcg(&d_logits[gid]) - __ldcg(&d_M) - __ldcg(&d_logS);
            }
            int tok = (t == 0) ? BOS : __ldcg(&d_token);
            x0 = emb_dec + (size_t)tok * HID;
        }

        for (int layer = 0; layer < NL; layer++) {
            const float* x = (layer == 0) ? x0 : &d_h[1 - p][0][0];
            const int wih = (dec ? 4 : 0) + layer * 2;
            const float* bih = (dec ? dec_bih : enc_bih) + layer * BOFF;
            const float* bhh = (dec ? dec_bhh : enc_bhh) + layer * BOFF;

            stage_T(sht, &d_h[p][layer][0]);
            stage_T(sxt, x);
            __syncthreads();

            float acc = dot2_bf16(d_Lbf[wih] + row_off, d_Lbf[wih + 1] + row_off,
                                  sxt, sht, lane);
            acc = warp_sum(acc);
            if (lane == 0) sg[wib] = acc;
            __syncthreads();

            if (tid < 2) {
                int un = bx * 2 + tid;
                float gi = sg[0 + tid] + bih[0 * HID + un] + bhh[0 * HID + un];
                float gf = sg[2 + tid] + bih[1 * HID + un] + bhh[1 * HID + un];
                float gg = sg[4 + tid] + bih[2 * HID + un] + bhh[2 * HID + un];
                float go = sg[6 + tid] + bih[3 * HID + un] + bhh[3 * HID + un];
                float i_ = sigmoidf_(gi);
                float f_ = sigmoidf_(gf);
                float g_ = tanhf(gg);
                float o_ = sigmoidf_(go);
                float cn = f_ * sc[layer][tid] + i_ * g_;
                sc[layer][tid] = cn;
                d_h[1 - p][layer][un] = o_ * tanhf(cn);
            }
            gsync();
        }

        // ---------- decoder: logits + fused finalize ----------
        if (dec) {
            stage_T(sht, &d_h[1 - p][NL - 1][0]);
            __syncthreads();

            float m = -3.0e38f, s = 0.f;
            int   mi = 0x7fffffff;
#pragma unroll
            for (int it = 0; it < 8; it++) {
                int row = it * (GRID * 8) + bx * 8 + wib;
                if (row < VOCAB) {
                    float acc = dot_bf16(d_Wbf + (size_t)row * HID, sht, lane);
                    acc = warp_sum(acc);
                    if (lane == 0) {
                        acc += out_b[row];
                        d_logits[row] = acc;
                        if (acc > m)       { s = s * expf(m - acc) + 1.f; m = acc; mi = row; }
                        else if (acc == m) { s += 1.f; if (row < mi) mi = row; }
                        else               { s += expf(acc - m); }
                    }
                }
            }
            if (lane == 0) { swm[wib] = m; sws[wib] = s; swi[wib] = mi; }
            __syncthreads();

            if (tid == 0) {
                float bm = swm[0], bs = sws[0]; int bi = swi[0];
#pragma unroll
                for (int k = 1; k < 8; k++) lse_merge(bm, bs, bi, swm[k], sws[k], swi[k]);
                d_pmax[bx] = bm;
                d_psum[bx] = bs;
                d_pidx[bx] = bi;
                __threadfence();
                unsigned int c = atomicAdd(&d_count, 1u);
                sflag = (c == GRID - 1) ? 1 : 0;
            }
            __syncthreads();

            if (sflag) {   // last block: global finalize over GRID partials
                float m2 = -3.0e38f, s2 = 0.f; int i2 = 0x7fffffff;
                for (int k = tid; k < GRID; k += NT)
                    lse_merge(m2, s2, i2, __ldcg(&d_pmax[k]), __ldcg(&d_psum[k]),
                              __ldcg(&d_pidx[k]));
                fm[tid] = m2; fs[tid] = s2; fi[tid] = i2;
                __syncthreads();
                for (int st = NT / 2; st; st >>= 1) {
                    if (tid < st)
                        lse_merge(fm[tid], fs[tid], fi[tid],
                                  fm[tid + st], fs[tid + st], fi[tid + st]);
                    __syncthreads();
                }
                if (tid == 0) {
                    d_M     = fm[0];
                    d_logS  = logf(fs[0]);
                    d_token = fi[0];
                    *(volatile unsigned int*)&d_count = 0u;
                    __threadfence();
                }
            }
            gsync();
        }

        p ^= 1;
    }

    // final step's log-probs
    {
        int gid = bx * NT + tid;
        if (gid < VOCAB)
            out[(size_t)(SEQ - 1) * VOCAB + gid] =
                __ldcg(&d_logits[gid]) - __ldcg(&d_M) - __ldcg(&d_logS);
    }
}

// ---------------- host orchestration ----------------
extern "C" void kernel_launch(void* const* d_in, const int* in_sizes, int n_in,
                              void* d_out, int out_size)
{
    (void)in_sizes; (void)n_in; (void)out_size;
    const int*   src     = (const int*)  d_in[0];
    const float* emb_enc = (const float*)d_in[2];
    const float* enc_Wih = (const float*)d_in[3];
    const float* enc_Whh = (const float*)d_in[4];
    const float* enc_bih = (const float*)d_in[5];
    const float* enc_bhh = (const float*)d_in[6];
    const float* emb_dec = (const float*)d_in[7];
    const float* dec_Wih = (const float*)d_in[8];
    const float* dec_Whh = (const float*)d_in[9];
    const float* dec_bih = (const float*)d_in[10];
    const float* dec_bhh = (const float*)d_in[11];
    const float* out_W   = (const float*)d_in[12];
    const float* out_b   = (const float*)d_in[13];
    float* out = (float*)d_out;

    convert_w_kernel<<<(int)((size_t)VOCAB * HID / 8 / 256), 256>>>(out_W);
    convert_lstm_kernel<<<dim3(2048, 8), 256>>>(enc_Wih, enc_Whh, dec_Wih, dec_Whh);

    seq2seq_kernel<<<GRID, NT>>>(src, emb_enc, enc_bih, enc_bhh,
                                 emb_dec, dec_bih, dec_bhh, out_b, out);
}

// round 7
// speedup vs baseline: 2.3010x; 1.1300x over previous
#include <cuda_runtime.h>
#include <cuda_bf16.h>
#include <math.h>

#define HID   1024
#define VOCAB 32000
#define SEQ   64
#define NL    2
#define BOS   1
#define GRID  512
#define NT    256

// ---------------- device scratch ----------------
__device__ float d_h0[2][HID];                         // layer-0 h, double-buffered
__device__ float d_h1[2][HID];                         // layer-1 h, double-buffered
__device__ float d_logits[VOCAB];
__device__ __nv_bfloat16 d_Wbf[(size_t)VOCAB * HID];   // bf16 out_W
// 0=eWih0 1=eWhh0 2=eWih1 3=eWhh1 4=dWih0 5=dWhh0 6=dWih1 7=dWhh1
__device__ __nv_bfloat16 d_Lbf[8][(size_t)4 * HID * HID];
__device__ float d_pmax[GRID];
__device__ float d_psum[GRID];
__device__ int   d_pidx[GRID];
__device__ unsigned int d_count = 0;
__device__ int   d_token;
__device__ float d_M, d_logS;
__device__ unsigned int g_gen = 0;
__device__ unsigned int g_cnt = 0;

// ---------------- fp32 -> bf16 converters ----------------
__device__ __forceinline__ uint4 cvt8(const float4 a, const float4 b) {
    __nv_bfloat162 r[4];
    r[0] = __nv_bfloat162(__float2bfloat16(a.x), __float2bfloat16(a.y));
    r[1] = __nv_bfloat162(__float2bfloat16(a.z), __float2bfloat16(a.w));
    r[2] = __nv_bfloat162(__float2bfloat16(b.x), __float2bfloat16(b.y));
    r[3] = __nv_bfloat162(__float2bfloat16(b.z), __float2bfloat16(b.w));
    return *(uint4*)r;
}

__global__ void __launch_bounds__(256)
convert_w_kernel(const float* __restrict__ W)
{
    size_t i = (size_t)blockIdx.x * 256 + threadIdx.x;
    const float4* w4 = (const float4*)W;
    ((uint4*)d_Wbf)[i] = cvt8(w4[2 * i], w4[2 * i + 1]);
}

// grid (2048, 8)
__global__ void __launch_bounds__(256)
convert_lstm_kernel(const float* __restrict__ eWih, const float* __restrict__ eWhh,
                    const float* __restrict__ dWih, const float* __restrict__ dWhh)
{
    const size_t WOFF = (size_t)4 * HID * HID;
    int m = blockIdx.y;
    const float* src;
    switch (m) {
        case 0: src = eWih;        break;
        case 1: src = eWhh;        break;
        case 2: src = eWih + WOFF; break;
        case 3: src = eWhh + WOFF; break;
        case 4: src = dWih;        break;
        case 5: src = dWhh;        break;
        case 6: src = dWih + WOFF; break;
        default: src = dWhh + WOFF; break;
    }
    size_t i = (size_t)blockIdx.x * 256 + threadIdx.x;
    const float4* s4 = (const float4*)src;
    ((uint4*)d_Lbf[m])[i] = cvt8(s4[2 * i], s4[2 * i + 1]);
}

// ---------------- helpers ----------------
__device__ __forceinline__ float sigmoidf_(float x) {
    return 1.0f / (1.0f + expf(-x));
}

// software grid barrier (all GRID blocks co-resident)
__device__ __forceinline__ void gsync() {
    __syncthreads();
    if (threadIdx.x == 0) {
        __threadfence();
        unsigned int gen = *(volatile unsigned int*)&g_gen;
        if (atomicAdd(&g_cnt, 1u) == GRID - 1) {
            *(volatile unsigned int*)&g_cnt = 0u;
            __threadfence();
            *(volatile unsigned int*)&g_gen = gen + 1;
        } else {
            while (*(volatile unsigned int*)&g_gen == gen) __nanosleep(32);
            __threadfence();
        }
    }
    __syncthreads();
}

// stage fp32 vector (L2-coherent read) into conflict-free transposed smem
__device__ __forceinline__ void stage_T(float (*dst)[128], const float* src) {
    float4 v = __ldcg(((const float4*)src) + threadIdx.x);
    int c = threadIdx.x * 4;
    dst[(c + 0) & 7][(c + 0) >> 3] = v.x;
    dst[(c + 1) & 7][(c + 1) >> 3] = v.y;
    dst[(c + 2) & 7][(c + 2) >> 3] = v.z;
    dst[(c + 3) & 7][(c + 3) >> 3] = v.w;
}

__device__ __forceinline__ float dot_bf16(const __nv_bfloat16* Wr,
                                          const float (*sv)[128], int lane)
{
    const uint4* w4 = (const uint4*)Wr;
    float acc = 0.f;
#pragma unroll
    for (int i = 0; i < 4; i++) {
        int idx = i * 32 + lane;
        uint4 wv = w4[idx];
        __nv_bfloat162* p = (__nv_bfloat162*)&wv;
#pragma unroll
        for (int k = 0; k < 4; k++) {
            float2 f = __bfloat1622float2(p[k]);
            acc += f.x * sv[2 * k][idx] + f.y * sv[2 * k + 1][idx];
        }
    }
    return acc;
}

__device__ __forceinline__ float dot2_bf16(const __nv_bfloat16* Wr, const __nv_bfloat16* Ur,
                                           const float (*sx)[128], const float (*sh)[128],
                                           int lane)
{
    const uint4* w4 = (const uint4*)Wr;
    const uint4* u4 = (const uint4*)Ur;
    float acc = 0.f;
#pragma unroll
    for (int i = 0; i < 4; i++) {
        int idx = i * 32 + lane;
        uint4 wv = w4[idx];
        uint4 uv = u4[idx];
        __nv_bfloat162* pw = (__nv_bfloat162*)&wv;
        __nv_bfloat162* pu = (__nv_bfloat162*)&uv;
#pragma unroll
        for (int k = 0; k < 4; k++) {
            float2 fw = __bfloat1622float2(pw[k]);
            float2 fu = __bfloat1622float2(pu[k]);
            acc += fw.x * sx[2 * k][idx] + fw.y * sx[2 * k + 1][idx];
            acc += fu.x * sh[2 * k][idx] + fu.y * sh[2 * k + 1][idx];
        }
    }
    return acc;
}

__device__ __forceinline__ float warp_sum(float v) {
#pragma unroll
    for (int off = 16; off; off >>= 1)
        v += __shfl_xor_sync(0xffffffffu, v, off);
    return v;
}

__device__ __forceinline__ void lse_merge(float& m1, float& s1, int& i1,
                                          float m2, float s2, int i2)
{
    if (m2 > m1)      { s1 = s1 * expf(m1 - m2) + s2; m1 = m2; i1 = i2; }
    else if (m2 == m1){ s1 += s2; if (i2 < i1) i1 = i2; }
    else              { s1 += s2 * expf(m2 - m1); }
}

// LSTM pointwise update: two threads (tid2 = 0 or 1) per block per layer
__device__ __forceinline__ void lstm_update(const float* sg, float* c_state,
                                            float* h_out, int un, int tid2,
                                            const float* bih, const float* bhh)
{
    float gi = sg[0 + tid2] + bih[0 * HID + un] + bhh[0 * HID + un];
    float gf = sg[2 + tid2] + bih[1 * HID + un] + bhh[1 * HID + un];
    float gg = sg[4 + tid2] + bih[2 * HID + un] + bhh[2 * HID + un];
    float go = sg[6 + tid2] + bih[3 * HID + un] + bhh[3 * HID + un];
    float i_ = sigmoidf_(gi);
    float f_ = sigmoidf_(gf);
    float g_ = tanhf(gg);
    float o_ = sigmoidf_(go);
    float cn = f_ * (*c_state) + i_ * g_;
    *c_state = cn;
    *h_out   = o_ * tanhf(cn);
}

// ---------------- persistent seq2seq kernel ----------------
__global__ void __launch_bounds__(NT, 4)
seq2seq_kernel(const int* __restrict__ src,
               const float* __restrict__ emb_enc,
               const float* __restrict__ enc_bih, const float* __restrict__ enc_bhh,
               const float* __restrict__ emb_dec,
               const float* __restrict__ dec_bih, const float* __restrict__ dec_bhh,
               const float* __restrict__ out_b,
               float* __restrict__ out)
{
    __shared__ float sxt0[8][128], sht0[8][128];
    __shared__ float sxt1[8][128], sht1[8][128];
    __shared__ float sg0[8], sg1[8];
    __shared__ float sc[NL][2];
    __shared__ float swm[8], sws[8];
    __shared__ int   swi[8];
    __shared__ float fm[NT], fs[NT];
    __shared__ int   fi[NT];
    __shared__ int   sflag;

    const int tid  = threadIdx.x;
    const int wib  = tid >> 5;
    const int lane = tid & 31;
    const int bx   = blockIdx.x;

    // ---- init state ----
    {
        int gid = bx * NT + tid;
        if (gid < 2 * HID) { ((float*)d_h0)[gid] = 0.0f; ((float*)d_h1)[gid] = 0.0f; }
        if (tid < 2) { sc[0][tid] = 0.0f; sc[1][tid] = 0.0f; }
    }
    gsync();

    const int u    = wib & 1;
    const int gate = wib >> 1;
    const int unit = bx * 2 + u;
    const size_t row_off = (size_t)(gate * HID + unit) * HID;
    const size_t BOFF = (size_t)4 * HID;

    // ================= encoder: wavefront over layers =================
    for (int k = 0; k <= SEQ; k++) {
        const bool doL0 = (k < SEQ);
        const bool doL1 = (k >= 1);

        if (doL0) {
            stage_T(sxt0, emb_enc + (size_t)src[k] * HID);
            stage_T(sht0, &d_h0[k & 1][0]);
        }
        if (doL1) {
            stage_T(sxt1, &d_h0[k & 1][0]);        // L0(k-1) output
            stage_T(sht1, &d_h1[(k - 1) & 1][0]);
        }
        __syncthreads();

        float acc0 = 0.f, acc1 = 0.f;
        if (doL0)
            acc0 = dot2_bf16(d_Lbf[0] + row_off, d_Lbf[1] + row_off, sxt0, sht0, lane);
        if (doL1)
            acc1 = dot2_bf16(d_Lbf[2] + row_off, d_Lbf[3] + row_off, sxt1, sht1, lane);
        acc0 = warp_sum(acc0);
        acc1 = warp_sum(acc1);
        if (lane == 0) { sg0[wib] = acc0; sg1[wib] = acc1; }
        __syncthreads();

        if (tid < 2 && doL0)
            lstm_update(sg0, &sc[0][tid], &d_h0[(k + 1) & 1][bx * 2 + tid],
                        bx * 2 + tid, tid, enc_bih, enc_bhh);
        if (tid >= 2 && tid < 4 && doL1)
            lstm_update(sg1, &sc[1][tid - 2], &d_h1[k & 1][bx * 2 + (tid - 2)],
                        bx * 2 + (tid - 2), tid - 2, enc_bih + BOFF, enc_bhh + BOFF);
        gsync();
    }
    // encoder final state: h0 in d_h0[0], h1 in d_h1[0]  (SEQ even)

    // ================= decoder =================
    for (int t = 0; t < SEQ; t++) {
        const int pr = t & 1;        // read parity
        const int pw = (t + 1) & 1;  // write parity

        // ---------- phase A: layer 0 (+ write previous step's logp) ----------
        if (t > 0) {
            int gid = bx * NT + tid;
            if (gid < VOCAB)
                out[(size_t)(t - 1) * VOCAB + gid] =
                    __ldcg(&d_logits[gid]) - __ldcg(&d_M) - __ldcg(&d_logS);
        }
        {
            int tok = (t == 0) ? BOS : __ldcg(&d_token);
            stage_T(sxt0, emb_dec + (size_t)tok * HID);
            stage_T(sht0, &d_h0[pr][0]);
            __syncthreads();

            float acc = dot2_bf16(d_Lbf[4] + row_off, d_Lbf[5] + row_off,
                                  sxt0, sht0, lane);
            acc = warp_sum(acc);
            if (lane == 0) sg0[wib] = acc;
            __syncthreads();
            if (tid < 2)
                lstm_update(sg0, &sc[0][tid], &d_h0[pw][bx * 2 + tid],
                            bx * 2 + tid, tid, dec_bih, dec_bhh);
            gsync();
        }

        // ---------- phase B: layer 1 ----------
        {
            stage_T(sxt1, &d_h0[pw][0]);
            stage_T(sht1, &d_h1[pr][0]);
            __syncthreads();

            float acc = dot2_bf16(d_Lbf[6] + row_off, d_Lbf[7] + row_off,
                                  sxt1, sht1, lane);
            acc = warp_sum(acc);
            if (lane == 0) sg1[wib] = acc;
            __syncthreads();
            if (tid < 2)
                lstm_update(sg1, &sc[1][tid], &d_h1[pw][bx * 2 + tid],
                            bx * 2 + tid, tid, dec_bih + BOFF, dec_bhh + BOFF);
            gsync();
        }

        // ---------- phase C: logits + finalize fused into barrier ----------
        {
            stage_T(sht0, &d_h1[pw][0]);
            __syncthreads();

            float m = -3.0e38f, s = 0.f;
            int   mi = 0x7fffffff;
#pragma unroll
            for (int it = 0; it < 8; it++) {
                int row = it * (GRID * 8) + bx * 8 + wib;
                if (row < VOCAB) {
                    float acc = dot_bf16(d_Wbf + (size_t)row * HID, sht0, lane);
                    acc = warp_sum(acc);
                    if (lane == 0) {
                        acc += out_b[row];
                        d_logits[row] = acc;
                        if (acc > m)       { s = s * expf(m - acc) + 1.f; m = acc; mi = row; }
                        else if (acc == m) { s += 1.f; if (row < mi) mi = row; }
                        else               { s += expf(acc - m); }
                    }
                }
            }
            if (lane == 0) { swm[wib] = m; sws[wib] = s; swi[wib] = mi; }
            __syncthreads();

            unsigned int gen = 0;
            if (tid == 0) {
                float bm = swm[0], bs = sws[0]; int bi = swi[0];
#pragma unroll
                for (int k = 1; k < 8; k++) lse_merge(bm, bs, bi, swm[k], sws[k], swi[k]);
                d_pmax[bx] = bm;
                d_psum[bx] = bs;
                d_pidx[bx] = bi;
                gen = *(volatile unsigned int*)&g_gen;
                __threadfence();
                unsigned int c = atomicAdd(&d_count, 1u);
                sflag = (c == GRID - 1) ? 1 : 0;
            }
            __syncthreads();

            if (sflag) {
                // last block: finalize, then RELEASE the barrier itself
                float m2 = -3.0e38f, s2 = 0.f; int i2 = 0x7fffffff;
                for (int k = tid; k < GRID; k += NT)
                    lse_merge(m2, s2, i2, __ldcg(&d_pmax[k]), __ldcg(&d_psum[k]),
                              __ldcg(&d_pidx[k]));
                fm[tid] = m2; fs[tid] = s2; fi[tid] = i2;
                __syncthreads();
                for (int st = NT / 2; st; st >>= 1) {
                    if (tid < st)
                        lse_merge(fm[tid], fs[tid], fi[tid],
                                  fm[tid + st], fs[tid + st], fi[tid + st]);
                    __syncthreads();
                }
                if (tid == 0) {
                    d_M     = fm[0];
                    d_logS  = logf(fs[0]);
                    d_token = fi[0];
                    *(volatile unsigned int*)&d_count = 0u;
                    __threadfence();
                    *(volatile unsigned int*)&g_gen = gen + 1;
                }
            } else {
                if (tid == 0) {
                    while (*(volatile unsigned int*)&g_gen == gen) __nanosleep(32);
                    __threadfence();
                }
            }
            __syncthreads();
        }
    }

    // final step's log-probs
    {
        int gid = bx * NT + tid;
        if (gid < VOCAB)
            out[(size_t)(SEQ - 1) * VOCAB + gid] =
                __ldcg(&d_logits[gid]) - __ldcg(&d_M) - __ldcg(&d_logS);
    }
}

// ---------------- host orchestration ----------------
extern "C" void kernel_launch(void* const* d_in, const int* in_sizes, int n_in,
                              void* d_out, int out_size)
{
    (void)in_sizes; (void)n_in; (void)out_size;
    const int*   src     = (const int*)  d_in[0];
    const float* emb_enc = (const float*)d_in[2];
    const float* enc_Wih = (const float*)d_in[3];
    const float* enc_Whh = (const float*)d_in[4];
    const float* enc_bih = (const float*)d_in[5];
    const float* enc_bhh = (const float*)d_in[6];
    const float* emb_dec = (const float*)d_in[7];
    const float* dec_Wih = (const float*)d_in[8];
    const float* dec_Whh = (const float*)d_in[9];
    const float* dec_bih = (const float*)d_in[10];
    const float* dec_bhh = (const float*)d_in[11];
    const float* out_W   = (const float*)d_in[12];
    const float* out_b   = (const float*)d_in[13];
    float* out = (float*)d_out;

    convert_w_kernel<<<(int)((size_t)VOCAB * HID / 8 / 256), 256>>>(out_W);
    convert_lstm_kernel<<<dim3(2048, 8), 256>>>(enc_Wih, enc_Whh, dec_Wih, dec_Whh);

    seq2seq_kernel<<<GRID, NT>>>(src, emb_enc, enc_bih, enc_bhh,
                                 emb_dec, dec_bih, dec_bhh, out_b, out);
}

// round 8
// speedup vs baseline: 2.4773x; 1.0766x over previous
#include <cuda_runtime.h>
#include <cuda_bf16.h>
#include <cuda_fp8.h>
#include <math.h>

#define HID   1024
#define VOCAB 32000
#define SEQ   64
#define NL    2
#define BOS   1
#define GRID  512
#define NT    256

#define W_SCALE  64.0f
#define W_INV    (1.0f / 64.0f)

// ---------------- device scratch ----------------
__device__ float d_h0[2][HID];
__device__ float d_h1[2][HID];
__device__ float d_logits[VOCAB];
__device__ unsigned char d_Wf8[(size_t)VOCAB * HID];   // fp8 out_W (32.7 MB)
// 0=eWih0 1=eWhh0 2=eWih1 3=eWhh1 4=dWih0 5=dWhh0 6=dWih1 7=dWhh1
__device__ unsigned char d_Lf8[8][(size_t)4 * HID * HID];
__device__ float d_pmax[GRID];
__device__ float d_psum[GRID];
__device__ int   d_pidx[GRID];
__device__ unsigned int d_count = 0;
__device__ int   d_token;
__device__ float d_M, d_logS;
__device__ unsigned int g_gen = 0;
__device__ unsigned int g_cnt = 0;

// ---------------- fp32 -> fp8 conversion ----------------
// thread handles 16 consecutive floats -> one uint4 of fp8
__device__ __forceinline__ uint4 cvt16_fp8(const float4* s4, size_t i) {
    __nv_fp8x2_storage_t r[8];
#pragma unroll
    for (int k = 0; k < 4; k++) {
        float4 a = s4[4 * i + k];
        float2 lo = make_float2(a.x * W_SCALE, a.y * W_SCALE);
        float2 hi = make_float2(a.z * W_SCALE, a.w * W_SCALE);
        r[2 * k + 0] = __nv_cvt_float2_to_fp8x2(lo, __NV_SATFINITE, __NV_E4M3);
        r[2 * k + 1] = __nv_cvt_float2_to_fp8x2(hi, __NV_SATFINITE, __NV_E4M3);
    }
    return *(uint4*)r;
}

__global__ void __launch_bounds__(256)
convert_w_kernel(const float* __restrict__ W)
{
    size_t i = (size_t)blockIdx.x * 256 + threadIdx.x;   // uint4 (16-elem) index
    ((uint4*)d_Wf8)[i] = cvt16_fp8((const float4*)W, i);
}

// grid (1024, 8)
__global__ void __launch_bounds__(256)
convert_lstm_kernel(const float* __restrict__ eWih, const float* __restrict__ eWhh,
                    const float* __restrict__ dWih, const float* __restrict__ dWhh)
{
    const size_t WOFF = (size_t)4 * HID * HID;
    int m = blockIdx.y;
    const float* src;
    switch (m) {
        case 0: src = eWih;        break;
        case 1: src = eWhh;        break;
        case 2: src = eWih + WOFF; break;
        case 3: src = eWhh + WOFF; break;
        case 4: src = dWih;        break;
        case 5: src = dWhh;        break;
        case 6: src = dWih + WOFF; break;
        default: src = dWhh + WOFF; break;
    }
    size_t i = (size_t)blockIdx.x * 256 + threadIdx.x;
    ((uint4*)d_Lf8[m])[i] = cvt16_fp8((const float4*)src, i);
}

// ---------------- helpers ----------------
__device__ __forceinline__ float sigmoidf_(float x) {
    return 1.0f / (1.0f + expf(-x));
}

__device__ __forceinline__ void gsync() {
    __syncthreads();
    if (threadIdx.x == 0) {
        __threadfence();
        unsigned int gen = *(volatile unsigned int*)&g_gen;
        if (atomicAdd(&g_cnt, 1u) == GRID - 1) {
            *(volatile unsigned int*)&g_cnt = 0u;
            __threadfence();
            *(volatile unsigned int*)&g_gen = gen + 1;
        } else {
            while (*(volatile unsigned int*)&g_gen == gen) __nanosleep(32);
            __threadfence();
        }
    }
    __syncthreads();
}

// stage fp32 vector into transposed smem: dst[c & 15][c >> 4] = v[c]
__device__ __forceinline__ void stage_T16(float (*dst)[64], const float* src) {
    float4 v = __ldcg(((const float4*)src) + threadIdx.x);
    int c = threadIdx.x * 4;
    dst[(c + 0) & 15][c >> 4] = v.x;
    dst[(c + 1) & 15][c >> 4] = v.y;
    dst[(c + 2) & 15][c >> 4] = v.z;
    dst[(c + 3) & 15][c >> 4] = v.w;
}

// fp8 row (1024 cols = 64 uint4) dot transposed fp32 vector
__device__ __forceinline__ float dot_fp8(const unsigned char* Wr,
                                         const float (*sv)[64], int lane)
{
    const uint4* w4 = (const uint4*)Wr;
    float acc = 0.f;
#pragma unroll
    for (int i = 0; i < 2; i++) {
        int idx = i * 32 + lane;
        uint4 wv = w4[idx];
        const __nv_fp8x2_storage_t* p = (const __nv_fp8x2_storage_t*)&wv;
#pragma unroll
        for (int k = 0; k < 8; k++) {
            __half2_raw hr = __nv_cvt_fp8x2_to_halfraw2(p[k], __NV_E4M3);
            float2 f = __half22float2(*(__half2*)&hr);
            acc += f.x * sv[2 * k][idx] + f.y * sv[2 * k + 1][idx];
        }
    }
    return acc;
}

__device__ __forceinline__ float dot2_fp8(const unsigned char* Wr, const unsigned char* Ur,
                                          const float (*sx)[64], const float (*sh)[64],
                                          int lane)
{
    const uint4* w4 = (const uint4*)Wr;
    const uint4* u4 = (const uint4*)Ur;
    float acc = 0.f;
#pragma unroll
    for (int i = 0; i < 2; i++) {
        int idx = i * 32 + lane;
        uint4 wv = w4[idx];
        uint4 uv = u4[idx];
        const __nv_fp8x2_storage_t* pw = (const __nv_fp8x2_storage_t*)&wv;
        const __nv_fp8x2_storage_t* pu = (const __nv_fp8x2_storage_t*)&uv;
#pragma unroll
        for (int k = 0; k < 8; k++) {
            __half2_raw hw = __nv_cvt_fp8x2_to_halfraw2(pw[k], __NV_E4M3);
            __half2_raw hu = __nv_cvt_fp8x2_to_halfraw2(pu[k], __NV_E4M3);
            float2 fw = __half22float2(*(__half2*)&hw);
            float2 fu = __half22float2(*(__half2*)&hu);
            acc += fw.x * sx[2 * k][idx] + fw.y * sx[2 * k + 1][idx];
            acc += fu.x * sh[2 * k][idx] + fu.y * sh[2 * k + 1][idx];
        }
    }
    return acc;
}

__device__ __forceinline__ float warp_sum(float v) {
#pragma unroll
    for (int off = 16; off; off >>= 1)
        v += __shfl_xor_sync(0xffffffffu, v, off);
    return v;
}

__device__ __forceinline__ void lse_merge(float& m1, float& s1, int& i1,
                                          float m2, float s2, int i2)
{
    if (m2 > m1)      { s1 = s1 * expf(m1 - m2) + s2; m1 = m2; i1 = i2; }
    else if (m2 == m1){ s1 += s2; if (i2 < i1) i1 = i2; }
    else              { s1 += s2 * expf(m2 - m1); }
}

__device__ __forceinline__ void lstm_update(const float* sg, float* c_state,
                                            float* h_out, int un, int tid2,
                                            const float* bih, const float* bhh)
{
    float gi = sg[0 + tid2] + bih[0 * HID + un] + bhh[0 * HID + un];
    float gf = sg[2 + tid2] + bih[1 * HID + un] + bhh[1 * HID + un];
    float gg = sg[4 + tid2] + bih[2 * HID + un] + bhh[2 * HID + un];
    float go = sg[6 + tid2] + bih[3 * HID + un] + bhh[3 * HID + un];
    float i_ = sigmoidf_(gi);
    float f_ = sigmoidf_(gf);
    float g_ = tanhf(gg);
    float o_ = sigmoidf_(go);
    float cn = f_ * (*c_state) + i_ * g_;
    *c_state = cn;
    *h_out   = o_ * tanhf(cn);
}

// ---------------- persistent seq2seq kernel ----------------
__global__ void __launch_bounds__(NT, 4)
seq2seq_kernel(const int* __restrict__ src,
               const float* __restrict__ emb_enc,
               const float* __restrict__ enc_bih, const float* __restrict__ enc_bhh,
               const float* __restrict__ emb_dec,
               const float* __restrict__ dec_bih, const float* __restrict__ dec_bhh,
               const float* __restrict__ out_b,
               float* __restrict__ out)
{
    __shared__ float sxt0[16][64], sht0[16][64];
    __shared__ float sxt1[16][64], sht1[16][64];
    __shared__ float sg0[8], sg1[8];
    __shared__ float sc[NL][2];
    __shared__ float swm[8], sws[8];
    __shared__ int   swi[8];
    __shared__ float fm[NT], fs[NT];
    __shared__ int   fi[NT];
    __shared__ int   sflag;

    const int tid  = threadIdx.x;
    const int wib  = tid >> 5;
    const int lane = tid & 31;
    const int bx   = blockIdx.x;

    {
        int gid = bx * NT + tid;
        if (gid < 2 * HID) { ((float*)d_h0)[gid] = 0.0f; ((float*)d_h1)[gid] = 0.0f; }
        if (tid < 2) { sc[0][tid] = 0.0f; sc[1][tid] = 0.0f; }
    }
    gsync();

    const int u    = wib & 1;
    const int gate = wib >> 1;
    const int unit = bx * 2 + u;
    const size_t row_off = (size_t)(gate * HID + unit) * HID;
    const size_t BOFF = (size_t)4 * HID;

    // ================= encoder: wavefront over layers =================
    for (int k = 0; k <= SEQ; k++) {
        const bool doL0 = (k < SEQ);
        const bool doL1 = (k >= 1);

        if (doL0) {
            stage_T16(sxt0, emb_enc + (size_t)src[k] * HID);
            stage_T16(sht0, &d_h0[k & 1][0]);
        }
        if (doL1) {
            stage_T16(sxt1, &d_h0[k & 1][0]);
            stage_T16(sht1, &d_h1[(k - 1) & 1][0]);
        }
        __syncthreads();

        float acc0 = 0.f, acc1 = 0.f;
        if (doL0)
            acc0 = dot2_fp8(d_Lf8[0] + row_off, d_Lf8[1] + row_off, sxt0, sht0, lane);
        if (doL1)
            acc1 = dot2_fp8(d_Lf8[2] + row_off, d_Lf8[3] + row_off, sxt1, sht1, lane);
        acc0 = warp_sum(acc0) * W_INV;
        acc1 = warp_sum(acc1) * W_INV;
        if (lane == 0) { sg0[wib] = acc0; sg1[wib] = acc1; }
        __syncthreads();

        if (tid < 2 && doL0)
            lstm_update(sg0, &sc[0][tid], &d_h0[(k + 1) & 1][bx * 2 + tid],
                        bx * 2 + tid, tid, enc_bih, enc_bhh);
        if (tid >= 2 && tid < 4 && doL1)
            lstm_update(sg1, &sc[1][tid - 2], &d_h1[k & 1][bx * 2 + (tid - 2)],
                        bx * 2 + (tid - 2), tid - 2, enc_bih + BOFF, enc_bhh + BOFF);
        gsync();
    }

    // ================= decoder =================
    for (int t = 0; t < SEQ; t++) {
        const int pr = t & 1;
        const int pw = (t + 1) & 1;

        // ---------- phase A: layer 0 (+ write previous step's logp) ----------
        if (t > 0) {
            int gid = bx * NT + tid;
            if (gid < VOCAB)
                out[(size_t)(t - 1) * VOCAB + gid] =
                    __ldcg(&d_logits[gid]) - __ldcg(&d_M) - __ldcg(&d_logS);
        }
        {
            int tok = (t == 0) ? BOS : __ldcg(&d_token);
            stage_T16(sxt0, emb_dec + (size_t)tok * HID);
            stage_T16(sht0, &d_h0[pr][0]);
            __syncthreads();

            float acc = dot2_fp8(d_Lf8[4] + row_off, d_Lf8[5] + row_off,
                                 sxt0, sht0, lane);
            acc = warp_sum(acc) * W_INV;
            if (lane == 0) sg0[wib] = acc;
            __syncthreads();
            if (tid < 2)
                lstm_update(sg0, &sc[0][tid], &d_h0[pw][bx * 2 + tid],
                            bx * 2 + tid, tid, dec_bih, dec_bhh);
            gsync();
        }

        // ---------- phase B: layer 1 ----------
        {
            stage_T16(sxt1, &d_h0[pw][0]);
            stage_T16(sht1, &d_h1[pr][0]);
            __syncthreads();

            float acc = dot2_fp8(d_Lf8[6] + row_off, d_Lf8[7] + row_off,
                                 sxt1, sht1, lane);
            acc = warp_sum(acc) * W_INV;
            if (lane == 0) sg1[wib] = acc;
            __syncthreads();
            if (tid < 2)
                lstm_update(sg1, &sc[1][tid], &d_h1[pw][bx * 2 + tid],
                            bx * 2 + tid, tid, dec_bih + BOFF, dec_bhh + BOFF);
            gsync();
        }

        // ---------- phase C: logits + finalize fused into barrier ----------
        {
            stage_T16(sht0, &d_h1[pw][0]);
            __syncthreads();

            float m = -3.0e38f, s = 0.f;
            int   mi = 0x7fffffff;
#pragma unroll
            for (int it = 0; it < 8; it++) {
                int row = it * (GRID * 8) + bx * 8 + wib;
                if (row < VOCAB) {
                    float acc = dot_fp8(d_Wf8 + (size_t)row * HID, sht0, lane);
                    acc = warp_sum(acc) * W_INV;
                    if (lane == 0) {
                        acc += out_b[row];
                        d_logits[row] = acc;
                        if (acc > m)       { s = s * expf(m - acc) + 1.f; m = acc; mi = row; }
                        else if (acc == m) { s += 1.f; if (row < mi) mi = row; }
                        else               { s += expf(acc - m); }
                    }
                }
            }
            if (lane == 0) { swm[wib] = m; sws[wib] = s; swi[wib] = mi; }
            __syncthreads();

            unsigned int gen = 0;
            if (tid == 0) {
                float bm = swm[0], bs = sws[0]; int bi = swi[0];
#pragma unroll
                for (int k = 1; k < 8; k++) lse_merge(bm, bs, bi, swm[k], sws[k], swi[k]);
                d_pmax[bx] = bm;
                d_psum[bx] = bs;
                d_pidx[bx] = bi;
                gen = *(volatile unsigned int*)&g_gen;
                __threadfence();
                unsigned int c = atomicAdd(&d_count, 1u);
                sflag = (c == GRID - 1) ? 1 : 0;
            }
            __syncthreads();

            if (sflag) {
                float m2 = -3.0e38f, s2 = 0.f; int i2 = 0x7fffffff;
                for (int k = tid; k < GRID; k += NT)
                    lse_merge(m2, s2, i2, __ldcg(&d_pmax[k]), __ldcg(&d_psum[k]),
                              __ldcg(&d_pidx[k]));
                fm[tid] = m2; fs[tid] = s2; fi[tid] = i2;
                __syncthreads();
                for (int st = NT / 2; st; st >>= 1) {
                    if (tid < st)
                        lse_merge(fm[tid], fs[tid], fi[tid],
                                  fm[tid + st], fs[tid + st], fi[tid + st]);
                    __syncthreads();
                }
                if (tid == 0) {
                    d_M     = fm[0];
                    d_logS  = logf(fs[0]);
                    d_token = fi[0];
                    *(volatile unsigned int*)&d_count = 0u;
                    __threadfence();
                    *(volatile unsigned int*)&g_gen = gen + 1;
                }
            } else {
                if (tid == 0) {
                    while (*(volatile unsigned int*)&g_gen == gen) __nanosleep(32);
                    __threadfence();
                }
            }
            __syncthreads();
        }
    }

    {
        int gid = bx * NT + tid;
        if (gid < VOCAB)
            out[(size_t)(SEQ - 1) * VOCAB + gid] =
                __ldcg(&d_logits[gid]) - __ldcg(&d_M) - __ldcg(&d_logS);
    }
}

// ---------------- host orchestration ----------------
extern "C" void kernel_launch(void* const* d_in, const int* in_sizes, int n_in,
                              void* d_out, int out_size)
{
    (void)in_sizes; (void)n_in; (void)out_size;
    const int*   src     = (const int*)  d_in[0];
    const float* emb_enc = (const float*)d_in[2];
    const float* enc_Wih = (const float*)d_in[3];
    const float* enc_Whh = (const float*)d_in[4];
    const float* enc_bih = (const float*)d_in[5];
    const float* enc_bhh = (const float*)d_in[6];
    const float* emb_dec = (const float*)d_in[7];
    const float* dec_Wih = (const float*)d_in[8];
    const float* dec_Whh = (const float*)d_in[9];
    const float* dec_bih = (const float*)d_in[10];
    const float* dec_bhh = (const float*)d_in[11];
    const float* out_W   = (const float*)d_in[12];
    const float* out_b   = (const float*)d_in[13];
    float* out = (float*)d_out;

    convert_w_kernel<<<(int)((size_t)VOCAB * HID / 16 / 256), 256>>>(out_W);
    convert_lstm_kernel<<<dim3(1024, 8), 256>>>(enc_Wih, enc_Whh, dec_Wih, dec_Whh);

    seq2seq_kernel<<<GRID, NT>>>(src, emb_enc, enc_bih, enc_bhh,
                                 emb_dec, dec_bih, dec_bhh, out_b, out);
}